// round 6
// baseline (speedup 1.0000x reference)
#include <cuda_runtime.h>
#include <math.h>

#define HW    16384
#define NMODE 512
#define PI2   6.28318530717958647692f

typedef unsigned long long ull;

// packed fp32x2 helpers (sm_100+: FFMA2)
__device__ __forceinline__ ull pk2(float a, float b) {
    ull r; asm("mov.b64 %0, {%1,%2};" : "=l"(r) : "f"(a), "f"(b)); return r;
}
__device__ __forceinline__ float2 upk(ull v) {
    float2 r; asm("mov.b64 {%0,%1}, %2;" : "=f"(r.x), "=f"(r.y) : "l"(v)); return r;
}
#define FMA2(d, a, b) asm("fma.rn.f32x2 %0, %1, %2, %0;" : "+l"(d) : "l"(a), "l"(b))

// ---- scratch (device globals; allocation-free kernel_launch) ----
__device__ __align__(16) float2 g_XF [2048 * NMODE];
__device__ __align__(16) float2 g_OF [3 * 2048 * NMODE];
__device__ __align__(16) float  g_kqv[100663296];     // [3][512][4][16384]
__device__ __align__(16) float  g_S  [32768];         // [8][64][64]
__device__ __align__(16) float  g_att[33554432];      // [8][256][16384]
__device__ __align__(16) float2 g_EOF[2048 * NMODE];

// ---------------- forward partial DFT: 128x128 plane -> 32x16 modes ----------
static const int SM_FWD = 128*129*4 + 128*16*8 + 256*4;   // 83456 B

__global__ void k_fwd_dft(const float* __restrict__ src, float2* __restrict__ dst) {
    extern __shared__ float sm[];
    float*  xs = sm;                               // [128][129]
    float2* T1 = (float2*)(sm + 128*129);          // [128][16]
    float*  ct = (float*)(T1 + 128*16);
    float*  st = ct + 128;
    const int tid = threadIdx.x;                   // 256
    const float* x = src + (size_t)blockIdx.x * HW;

    if (tid < 128) { float a = (float)tid * (PI2/128.f); ct[tid] = cosf(a); st[tid] = sinf(a); }
    for (int i = tid; i < HW; i += 256) xs[(i >> 7)*129 + (i & 127)] = x[i];
    __syncthreads();

    {   // phase 1: T1[h][m2] = sum_w x[h][w] e^{-2pi i m2 w/128}
        int h = tid >> 1, m2b = (tid & 1) * 8;
        float2 acc[8];
        #pragma unroll
        for (int j = 0; j < 8; j++) acc[j] = make_float2(0.f, 0.f);
        for (int w = 0; w < 128; w++) {
            float xv = xs[h*129 + w];
            #pragma unroll
            for (int j = 0; j < 8; j++) {
                int idx = ((m2b + j) * w) & 127;
                acc[j].x += xv * ct[idx];
                acc[j].y -= xv * st[idx];
            }
        }
        #pragma unroll
        for (int j = 0; j < 8; j++) T1[h*16 + m2b + j] = acc[j];
    }
    __syncthreads();

    // phase 2: fold h with row-mode twiddles (rows 0..15 and 112..127)
    #pragma unroll
    for (int rep = 0; rep < 2; rep++) {
        int om  = tid*2 + rep;
        int m1i = om >> 4, m2 = om & 15;
        int r   = (m1i < 16) ? m1i : (m1i + 96);
        float sx = 0.f, sy = 0.f;
        for (int h = 0; h < 128; h++) {
            int idx = (r * h) & 127;
            float c = ct[idx], s = st[idx];
            float2 t = T1[h*16 + m2];
            sx += t.x*c + t.y*s;
            sy += t.y*c - t.x*s;
        }
        dst[(size_t)blockIdx.x * NMODE + om] = make_float2(sx*(1.f/16384.f), sy*(1.f/16384.f));
    }
}

// ---------------- kqv spectral multiply ----------------
__global__ void k_spec_kqv(const float* __restrict__ w1r, const float* __restrict__ w1i,
                           const float* __restrict__ w2r, const float* __restrict__ w2i) {
    int s = blockIdx.x >> 9, n = blockIdx.x & 511;
    int m = threadIdx.x;                 // 512
    bool top = m < 256;
    int mm = top ? m : (m - 256);
    const float* wr = top ? w1r : w2r;
    const float* wi = top ? w1i : w2i;

    float2 xv[4];
    #pragma unroll
    for (int i = 0; i < 4; i++) xv[i] = g_XF[(size_t)(n*4 + i) * NMODE + m];

    #pragma unroll
    for (int o = 0; o < 4; o++) {
        float ax = 0.f, ay = 0.f;
        #pragma unroll
        for (int i = 0; i < 4; i++) {
            float a = wr[s*4096 + (i*4 + o)*256 + mm];
            float b = wi[s*4096 + (i*4 + o)*256 + mm];
            ax += xv[i].x*a - xv[i].y*b;
            ay += xv[i].x*b + xv[i].y*a;
        }
        g_OF[((size_t)(s*512 + n)*4 + o) * NMODE + m] = make_float2(ax, ay);
    }
}

// ---------------- kqv inverse partial DFT + pointwise skip -------------------
static const int SM_IDFTK = (2048 + 8192)*8 + 256*4 + 16*4;   // 83008 B

__global__ void k_idft_kqv(const float* __restrict__ x, const float* __restrict__ skip) {
    extern __shared__ float sm[];
    float2* OFs = (float2*)sm;                 // [4][32][16]
    float2* U   = OFs + 2048;                  // [4][128][16]
    float*  ct  = (float*)(U + 8192);
    float*  st  = ct + 128;
    float*  sk  = st + 128;                    // [4][4] (o,i)
    const int tid = threadIdx.x;               // 256
    const int s = blockIdx.x >> 9, n = blockIdx.x & 511;

    if (tid < 128) { float a = (float)tid * (PI2/128.f); ct[tid] = cosf(a); st[tid] = sinf(a); }
    if (tid < 16)  sk[tid] = skip[s*16 + tid];
    for (int i = tid; i < 2048; i += 256)
        OFs[i] = g_OF[((size_t)(s*512 + n)*4) * NMODE + i];
    __syncthreads();

    // phase 1: U[o][h][m2] = a(m2) * sum_{m1} OF[o][m1][m2] e^{+2pi i r h/128}
    for (int e = tid; e < 8192; e += 256) {
        int o = e >> 11, rem = e & 2047, h = rem >> 4, m2 = rem & 15;
        float ux = 0.f, uy = 0.f;
        #pragma unroll
        for (int m1i = 0; m1i < 32; m1i++) {
            int r = (m1i < 16) ? m1i : (m1i + 96);
            int idx = (r * h) & 127;
            float c = ct[idx], sn = st[idx];
            float2 X = OFs[o*512 + m1i*16 + m2];
            ux += X.x*c  - X.y*sn;
            uy += X.x*sn + X.y*c;
        }
        float a = (m2 == 0) ? 1.f : 2.f;
        U[e] = make_float2(ux*a, uy*a);
    }
    __syncthreads();

    // phase 2: expand over m2 (Re part) via packed FMA2 + skip
    int w = tid & 127, o0 = (tid >> 7) * 2;
    ull tw2[16];
    #pragma unroll
    for (int m2 = 0; m2 < 16; m2++) {
        int idx = (m2*w) & 127;
        tw2[m2] = pk2(ct[idx], -st[idx]);
    }
    float s00 = sk[o0*4+0], s01 = sk[o0*4+1], s02 = sk[o0*4+2], s03 = sk[o0*4+3];
    float s10 = sk[o0*4+4], s11 = sk[o0*4+5], s12 = sk[o0*4+6], s13 = sk[o0*4+7];
    size_t outbase = ((size_t)(s*512 + n)*4 + o0) * HW;
    size_t xbase   = (size_t)n * 4 * HW;

    for (int h = 0; h < 128; h++) {
        const ull* U0 = (const ull*)(U + (o0 << 11) + (h << 4));
        const ull* U1 = (const ull*)(U + ((o0+1) << 11) + (h << 4));
        ull a0 = 0, a1 = 0;
        #pragma unroll
        for (int m2 = 0; m2 < 16; m2++) {
            FMA2(a0, U0[m2], tw2[m2]);
            FMA2(a1, U1[m2], tw2[m2]);
        }
        float2 r0 = upk(a0), r1 = upk(a1);
        float v0 = r0.x + r0.y, v1 = r1.x + r1.y;
        int p = (h << 7) + w;
        float x0 = x[xbase + p],        x1 = x[xbase + HW + p];
        float x2 = x[xbase + 2*HW + p], x3 = x[xbase + 3*HW + p];
        v0 += s00*x0 + s01*x1 + s02*x2 + s03*x3;
        v1 += s10*x0 + s11*x1 + s12*x2 + s13*x3;
        g_kqv[outbase + p]      = v0;
        g_kqv[outbase + HW + p] = v1;
    }
}

// ---------------- attention --------------------------------------------------
__global__ void k_zero(int off) {
    g_S[off + blockIdx.x*256 + threadIdx.x] = 0.f;
}

static const int SM_SCORES = 2*64*258*4;   // 132096 B (258 stride: 8B-aligned rows+pairs)

__global__ void k_scores() {
    extern __shared__ float sm[];
    float* qs = sm;             // [64][258]
    float* ks = sm + 64*258;
    const int b = blockIdx.y, ch = blockIdx.x, tid = threadIdx.x;
    size_t qoff = ((size_t)512 + (size_t)b*64) * 65536 + (size_t)ch*256;  // q = kqv[1]
    size_t koff = ((size_t)b*64) * 65536 + (size_t)ch*256;                // k = kqv[0]
    for (int i = tid; i < 16384; i += 256) {
        int t = i >> 8, j = i & 255;
        qs[t*258 + j] = g_kqv[qoff + (size_t)t*65536 + j];
        ks[t*258 + j] = g_kqv[koff + (size_t)t*65536 + j];
    }
    __syncthreads();
    int t = tid >> 2, s0 = (tid & 3) * 16;
    ull acc[16];
    #pragma unroll
    for (int j = 0; j < 16; j++) acc[j] = 0;
    const ull* qrow = (const ull*)(qs + t*258);
    for (int kk = 0; kk < 128; kk++) {
        ull q2 = qrow[kk];
        #pragma unroll
        for (int j = 0; j < 16; j++) {
            ull k2 = *(const ull*)(ks + (s0 + j)*258 + 2*kk);
            FMA2(acc[j], q2, k2);
        }
    }
    #pragma unroll
    for (int j = 0; j < 16; j++) {
        float2 r = upk(acc[j]);
        atomicAdd(&g_S[(b*64 + t)*64 + s0 + j], (r.x + r.y) * (1.f/65536.f));
    }
}

__global__ void k_softmax() {
    int b = blockIdx.x, t = threadIdx.x;           // 8 x 64
    float* row = &g_S[(b*64 + t)*64];
    float mx = -1e30f;
    for (int s = 0; s < 64; s++) mx = fmaxf(mx, row[s]);
    float sum = 0.f;
    for (int s = 0; s < 64; s++) { float v = expf(row[s] - mx); row[s] = v; sum += v; }
    float inv = 1.f / sum;
    for (int s = 0; s < 64; s++) row[s] *= inv;
}

// ---- REVERTED to Round-2 passing version (bisect) ----
__global__ void k_attnv() {
    __shared__ float As[4096];
    const int b = blockIdx.y, tid = threadIdx.x;
    const int p = blockIdx.x * 256 + tid;          // global feature 0..65535
    for (int i = tid; i < 4096; i += 256) As[i] = g_S[b*4096 + i];
    __syncthreads();
    float acc[64];
    #pragma unroll
    for (int t = 0; t < 64; t++) acc[t] = 0.f;
    size_t vbase = ((size_t)1024 + (size_t)b*64) * 65536 + p;   // v = kqv[2]
    for (int s = 0; s < 64; s++) {
        float vv = g_kqv[vbase + (size_t)s*65536];
        #pragma unroll
        for (int t = 0; t < 64; t++) acc[t] += As[t*64 + s] * vv;
    }
    size_t obase = (size_t)b * 4194304 + p;
    #pragma unroll
    for (int t = 0; t < 64; t++) g_att[obase + (size_t)t*65536] = acc[t];
}

// ---------------- InstanceNorm2d + exact GELU (in place) --------------------
__global__ void k_inorm() {
    __shared__ float w1s[8], w2s[8];
    float* ptr = g_att + (size_t)blockIdx.x * HW;
    const int tid = threadIdx.x;
    float s1 = 0.f, s2 = 0.f;
    for (int i = tid; i < HW; i += 256) { float v = ptr[i]; s1 += v; s2 += v*v; }
    for (int off = 16; off; off >>= 1) {
        s1 += __shfl_down_sync(0xffffffffu, s1, off);
        s2 += __shfl_down_sync(0xffffffffu, s2, off);
    }
    if ((tid & 31) == 0) { w1s[tid >> 5] = s1; w2s[tid >> 5] = s2; }
    __syncthreads();
    if (tid == 0) {
        float a = 0.f, c = 0.f;
        for (int i = 0; i < 8; i++) { a += w1s[i]; c += w2s[i]; }
        w1s[0] = a * (1.f/HW); w2s[0] = c * (1.f/HW);
    }
    __syncthreads();
    float mu = w1s[0];
    float inv = rsqrtf(w2s[0] - mu*mu + 1e-5f);
    for (int i = tid; i < HW; i += 256) {
        float v = (ptr[i] - mu) * inv;
        ptr[i] = v * normcdff(v);
    }
}

// ---------------- end spectral multiply -------------------------------------
__global__ void k_spec_end(const float* __restrict__ w1r, const float* __restrict__ w1i,
                           const float* __restrict__ w2r, const float* __restrict__ w2i) {
    const int m = threadIdx.x;                 // 512
    const int o0 = blockIdx.x * 2;             // 128 blocks
    bool top = m < 256;
    int mm = top ? m : (m - 256);
    const float* wr = top ? w1r : w2r;
    const float* wi = top ? w1i : w2i;
    float2 a0[8], a1[8];
    #pragma unroll
    for (int b = 0; b < 8; b++) { a0[b] = make_float2(0.f,0.f); a1[b] = make_float2(0.f,0.f); }
    for (int i = 0; i < 256; i++) {
        float wr0 = wr[((size_t)i*256 + o0    )*256 + mm];
        float wi0 = wi[((size_t)i*256 + o0    )*256 + mm];
        float wr1 = wr[((size_t)i*256 + o0 + 1)*256 + mm];
        float wi1 = wi[((size_t)i*256 + o0 + 1)*256 + mm];
        #pragma unroll
        for (int b = 0; b < 8; b++) {
            float2 xv = g_XF[((size_t)(b*256 + i)) * NMODE + m];
            a0[b].x += xv.x*wr0 - xv.y*wi0;  a0[b].y += xv.x*wi0 + xv.y*wr0;
            a1[b].x += xv.x*wr1 - xv.y*wi1;  a1[b].y += xv.x*wi1 + xv.y*wr1;
        }
    }
    #pragma unroll
    for (int b = 0; b < 8; b++) {
        g_EOF[((size_t)(b*256 + o0    )) * NMODE + m] = a0[b];
        g_EOF[((size_t)(b*256 + o0 + 1)) * NMODE + m] = a1[b];
    }
}

// ---------------- end inverse partial DFT -> d_out --------------------------
__global__ void k_idft_end(float* __restrict__ out) {
    __shared__ float2 OFs[512];
    __shared__ float2 U[2048];
    __shared__ float ct[128], st[128];
    const int tid = threadIdx.x;               // 256
    const int plane = blockIdx.x;              // 2048
    if (tid < 128) { float a = (float)tid * (PI2/128.f); ct[tid] = cosf(a); st[tid] = sinf(a); }
    for (int i = tid; i < 512; i += 256) OFs[i] = g_EOF[(size_t)plane*512 + i];
    __syncthreads();
    for (int e = tid; e < 2048; e += 256) {
        int h = e >> 4, m2 = e & 15;
        float ux = 0.f, uy = 0.f;
        #pragma unroll
        for (int m1i = 0; m1i < 32; m1i++) {
            int r = (m1i < 16) ? m1i : (m1i + 96);
            int idx = (r * h) & 127;
            float c = ct[idx], sn = st[idx];
            float2 X = OFs[m1i*16 + m2];
            ux += X.x*c  - X.y*sn;
            uy += X.x*sn + X.y*c;
        }
        float a = (m2 == 0) ? 1.f : 2.f;
        U[e] = make_float2(ux*a, uy*a);
    }
    __syncthreads();
    int w = tid & 127, h0 = (tid >> 7) * 64;
    ull tw2[16];
    #pragma unroll
    for (int m2 = 0; m2 < 16; m2++) {
        int idx = (m2*w) & 127;
        tw2[m2] = pk2(ct[idx], -st[idx]);
    }
    for (int h = h0; h < h0 + 64; h++) {
        const ull* Up = (const ull*)(U + (h << 4));
        ull a2 = 0;
        #pragma unroll
        for (int m2 = 0; m2 < 16; m2++) FMA2(a2, Up[m2], tw2[m2]);
        float2 r = upk(a2);
        out[(size_t)plane*HW + (h << 7) + w] = r.x + r.y;
    }
}

// ---- REVERTED to Round-2 passing version (bisect) ----
__global__ void k_endskip(const float* __restrict__ skip, float* __restrict__ out) {
    __shared__ float Ss[32][65];
    __shared__ float Gs[32][128];
    const int b = blockIdx.z, o0 = blockIdx.y * 64, p0 = blockIdx.x * 128;
    const int tid = threadIdx.x;
    const int px = tid & 31, oy = tid >> 5;
    float acc[8][4];
    #pragma unroll
    for (int j = 0; j < 8; j++)
        #pragma unroll
        for (int jj = 0; jj < 4; jj++) acc[j][jj] = 0.f;

    for (int kc = 0; kc < 256; kc += 32) {
        for (int i = tid; i < 2048; i += 256) {
            int orow = i >> 5, ic = i & 31;
            Ss[ic][orow] = skip[(size_t)(o0 + orow)*256 + kc + ic];
        }
        for (int i = tid; i < 4096; i += 256) {
            int ir = i >> 7, c = i & 127;
            Gs[ir][c] = g_att[((size_t)b*256 + kc + ir) * HW + p0 + c];
        }
        __syncthreads();
        #pragma unroll 8
        for (int k = 0; k < 32; k++) {
            float gv[4], sv[8];
            #pragma unroll
            for (int jj = 0; jj < 4; jj++) gv[jj] = Gs[k][px + 32*jj];
            #pragma unroll
            for (int j = 0; j < 8; j++) sv[j] = Ss[k][oy + 8*j];
            #pragma unroll
            for (int j = 0; j < 8; j++)
                #pragma unroll
                for (int jj = 0; jj < 4; jj++) acc[j][jj] += sv[j] * gv[jj];
        }
        __syncthreads();
    }
    #pragma unroll
    for (int j = 0; j < 8; j++)
        #pragma unroll
        for (int jj = 0; jj < 4; jj++) {
            size_t oidx = ((size_t)b*256 + o0 + oy + 8*j) * HW + p0 + px + 32*jj;
            out[oidx] += acc[j][jj];
        }
}

// ---------------- launch -----------------------------------------------------
extern "C" void kernel_launch(void* const* d_in, const int* in_sizes, int n_in,
                              void* d_out, int out_size) {
    const float* x        = (const float*)d_in[0];
    const float* kqv_w1r  = (const float*)d_in[1];
    const float* kqv_w1i  = (const float*)d_in[2];
    const float* kqv_w2r  = (const float*)d_in[3];
    const float* kqv_w2i  = (const float*)d_in[4];
    const float* kqv_skip = (const float*)d_in[5];
    const float* end_w1r  = (const float*)d_in[6];
    const float* end_w1i  = (const float*)d_in[7];
    const float* end_w2r  = (const float*)d_in[8];
    const float* end_w2i  = (const float*)d_in[9];
    const float* end_skip = (const float*)d_in[10];
    float* out = (float*)d_out;

    cudaFuncSetAttribute(k_fwd_dft,  cudaFuncAttributeMaxDynamicSharedMemorySize, SM_FWD);
    cudaFuncSetAttribute(k_idft_kqv, cudaFuncAttributeMaxDynamicSharedMemorySize, SM_IDFTK);
    cudaFuncSetAttribute(k_scores,   cudaFuncAttributeMaxDynamicSharedMemorySize, SM_SCORES);

    float2* gXF;  cudaGetSymbolAddress((void**)&gXF,  g_XF);
    float*  gAtt; cudaGetSymbolAddress((void**)&gAtt, g_att);

    // stage 1  (launch order arranged so ncu -s 5 -c 1 profiles k_scores)
    k_fwd_dft<<<2048, 256, SM_FWD>>>(x, gXF);                       // 1
    k_spec_kqv<<<1536, 512>>>(kqv_w1r, kqv_w1i, kqv_w2r, kqv_w2i);  // 2
    k_idft_kqv<<<1536, 256, SM_IDFTK>>>(x, kqv_skip);               // 3
    k_zero<<<64, 256>>>(0);                                         // 4
    k_zero<<<64, 256>>>(16384);                                     // 5
    k_scores<<<dim3(256, 8), 256, SM_SCORES>>>();                   // 6 <- profiled
    k_softmax<<<8, 64>>>();
    k_attnv<<<dim3(256, 8), 256>>>();

    // instance norm + gelu
    k_inorm<<<2048, 256>>>();

    // stage 2: end FNO block
    k_fwd_dft<<<2048, 256, SM_FWD>>>(gAtt, gXF);
    k_spec_end<<<128, 512>>>(end_w1r, end_w1i, end_w2r, end_w2i);
    k_idft_end<<<2048, 256>>>(out);
    k_endskip<<<dim3(128, 4, 8), 256>>>(end_skip, out);
}

// round 9
// speedup vs baseline: 1.2011x; 1.2011x over previous
#include <cuda_runtime.h>
#include <math.h>

#define HW    16384
#define NMODE 512
#define PI2   6.28318530717958647692f

typedef unsigned long long ull;

// packed fp32x2 helpers (sm_100+: FFMA2)
__device__ __forceinline__ ull pk2(float a, float b) {
    ull r; asm("mov.b64 %0, {%1,%2};" : "=l"(r) : "f"(a), "f"(b)); return r;
}
__device__ __forceinline__ float2 upk(ull v) {
    float2 r; asm("mov.b64 {%0,%1}, %2;" : "=f"(r.x), "=f"(r.y) : "l"(v)); return r;
}
#define FMA2(d, a, b) asm("fma.rn.f32x2 %0, %1, %2, %0;" : "+l"(d) : "l"(a), "l"(b))

// ---- scratch (device globals; 16B-aligned for 8B vector accesses) ----
__device__ __align__(16) float2 g_XF [2048 * NMODE];
__device__ __align__(16) float2 g_OF [3 * 2048 * NMODE];
__device__ __align__(16) float  g_kqv[100663296];     // [3][512][4][16384]
__device__ __align__(16) float  g_S  [32768];         // [8][64][64]
__device__ __align__(16) float  g_att[33554432];      // [8][256][16384]
__device__ __align__(16) float2 g_EOF[2048 * NMODE];

// ---------------- forward partial DFT: 128x128 plane -> 32x16 modes ----------
static const int SM_FWD = 128*129*4 + 128*16*8 + 256*4;   // 83456 B

__global__ void k_fwd_dft(const float* __restrict__ src, float2* __restrict__ dst) {
    extern __shared__ float sm[];
    float*  xs = sm;                               // [128][129]
    float2* T1 = (float2*)(sm + 128*129);          // [128][16]
    float*  ct = (float*)(T1 + 128*16);
    float*  st = ct + 128;
    const int tid = threadIdx.x;                   // 256
    const float* x = src + (size_t)blockIdx.x * HW;

    if (tid < 128) { float a = (float)tid * (PI2/128.f); ct[tid] = cosf(a); st[tid] = sinf(a); }
    for (int i = tid; i < HW; i += 256) xs[(i >> 7)*129 + (i & 127)] = x[i];
    __syncthreads();

    {   // phase 1: T1[h][m2] = sum_w x[h][w] e^{-2pi i m2 w/128}
        int h = tid >> 1, m2b = (tid & 1) * 8;
        float2 acc[8];
        #pragma unroll
        for (int j = 0; j < 8; j++) acc[j] = make_float2(0.f, 0.f);
        for (int w = 0; w < 128; w++) {
            float xv = xs[h*129 + w];
            #pragma unroll
            for (int j = 0; j < 8; j++) {
                int idx = ((m2b + j) * w) & 127;
                acc[j].x += xv * ct[idx];
                acc[j].y -= xv * st[idx];
            }
        }
        #pragma unroll
        for (int j = 0; j < 8; j++) T1[h*16 + m2b + j] = acc[j];
    }
    __syncthreads();

    // phase 2: fold h with row-mode twiddles (rows 0..15 and 112..127)
    #pragma unroll
    for (int rep = 0; rep < 2; rep++) {
        int om  = tid*2 + rep;
        int m1i = om >> 4, m2 = om & 15;
        int r   = (m1i < 16) ? m1i : (m1i + 96);
        float sx = 0.f, sy = 0.f;
        for (int h = 0; h < 128; h++) {
            int idx = (r * h) & 127;
            float c = ct[idx], s = st[idx];
            float2 t = T1[h*16 + m2];
            sx += t.x*c + t.y*s;
            sy += t.y*c - t.x*s;
        }
        dst[(size_t)blockIdx.x * NMODE + om] = make_float2(sx*(1.f/16384.f), sy*(1.f/16384.f));
    }
}

// ---------------- kqv spectral multiply ----------------
__global__ void k_spec_kqv(const float* __restrict__ w1r, const float* __restrict__ w1i,
                           const float* __restrict__ w2r, const float* __restrict__ w2i) {
    int s = blockIdx.x >> 9, n = blockIdx.x & 511;
    int m = threadIdx.x;                 // 512
    bool top = m < 256;
    int mm = top ? m : (m - 256);
    const float* wr = top ? w1r : w2r;
    const float* wi = top ? w1i : w2i;

    float2 xv[4];
    #pragma unroll
    for (int i = 0; i < 4; i++) xv[i] = g_XF[(size_t)(n*4 + i) * NMODE + m];

    #pragma unroll
    for (int o = 0; o < 4; o++) {
        float ax = 0.f, ay = 0.f;
        #pragma unroll
        for (int i = 0; i < 4; i++) {
            float a = wr[s*4096 + (i*4 + o)*256 + mm];
            float b = wi[s*4096 + (i*4 + o)*256 + mm];
            ax += xv[i].x*a - xv[i].y*b;
            ay += xv[i].x*b + xv[i].y*a;
        }
        g_OF[((size_t)(s*512 + n)*4 + o) * NMODE + m] = make_float2(ax, ay);
    }
}

// ---------------- kqv inverse partial DFT + pointwise skip -------------------
static const int SM_IDFTK = (2048 + 8192)*8 + 256*4 + 16*4;   // 83008 B

__global__ void k_idft_kqv(const float* __restrict__ x, const float* __restrict__ skip) {
    extern __shared__ float sm[];
    float2* OFs = (float2*)sm;                 // [4][32][16]
    float2* U   = OFs + 2048;                  // [4][128][16]
    float*  ct  = (float*)(U + 8192);
    float*  st  = ct + 128;
    float*  sk  = st + 128;                    // [4][4] (o,i)
    const int tid = threadIdx.x;               // 256
    const int s = blockIdx.x >> 9, n = blockIdx.x & 511;

    if (tid < 128) { float a = (float)tid * (PI2/128.f); ct[tid] = cosf(a); st[tid] = sinf(a); }
    if (tid < 16)  sk[tid] = skip[s*16 + tid];
    for (int i = tid; i < 2048; i += 256)
        OFs[i] = g_OF[((size_t)(s*512 + n)*4) * NMODE + i];
    __syncthreads();

    // phase 1: U[o][h][m2] = a(m2) * sum_{m1} OF[o][m1][m2] e^{+2pi i r h/128}
    for (int e = tid; e < 8192; e += 256) {
        int o = e >> 11, rem = e & 2047, h = rem >> 4, m2 = rem & 15;
        float ux = 0.f, uy = 0.f;
        #pragma unroll
        for (int m1i = 0; m1i < 32; m1i++) {
            int r = (m1i < 16) ? m1i : (m1i + 96);
            int idx = (r * h) & 127;
            float c = ct[idx], sn = st[idx];
            float2 X = OFs[o*512 + m1i*16 + m2];
            ux += X.x*c  - X.y*sn;
            uy += X.x*sn + X.y*c;
        }
        float a = (m2 == 0) ? 1.f : 2.f;
        U[e] = make_float2(ux*a, uy*a);
    }
    __syncthreads();

    // phase 2: expand over m2 (Re part) via packed FMA2 + skip
    int w = tid & 127, o0 = (tid >> 7) * 2;
    ull tw2[16];
    #pragma unroll
    for (int m2 = 0; m2 < 16; m2++) {
        int idx = (m2*w) & 127;
        tw2[m2] = pk2(ct[idx], -st[idx]);
    }
    float s00 = sk[o0*4+0], s01 = sk[o0*4+1], s02 = sk[o0*4+2], s03 = sk[o0*4+3];
    float s10 = sk[o0*4+4], s11 = sk[o0*4+5], s12 = sk[o0*4+6], s13 = sk[o0*4+7];
    size_t outbase = ((size_t)(s*512 + n)*4 + o0) * HW;
    size_t xbase   = (size_t)n * 4 * HW;

    for (int h = 0; h < 128; h++) {
        const ull* U0 = (const ull*)(U + (o0 << 11) + (h << 4));
        const ull* U1 = (const ull*)(U + ((o0+1) << 11) + (h << 4));
        ull a0 = 0, a1 = 0;
        #pragma unroll
        for (int m2 = 0; m2 < 16; m2++) {
            FMA2(a0, U0[m2], tw2[m2]);
            FMA2(a1, U1[m2], tw2[m2]);
        }
        float2 r0 = upk(a0), r1 = upk(a1);
        float v0 = r0.x + r0.y, v1 = r1.x + r1.y;
        int p = (h << 7) + w;
        float x0 = x[xbase + p],        x1 = x[xbase + HW + p];
        float x2 = x[xbase + 2*HW + p], x3 = x[xbase + 3*HW + p];
        v0 += s00*x0 + s01*x1 + s02*x2 + s03*x3;
        v1 += s10*x0 + s11*x1 + s12*x2 + s13*x3;
        g_kqv[outbase + p]      = v0;
        g_kqv[outbase + HW + p] = v1;
    }
}

// ---------------- attention --------------------------------------------------
__global__ void k_zero(int off) {
    g_S[off + blockIdx.x*256 + threadIdx.x] = 0.f;
}

static const int SM_SCORES = 2*64*258*4;   // 132096 B

__global__ void k_scores() {
    extern __shared__ float sm[];
    float* qs = sm;             // [64][258]  (row stride 258 floats = 129 8B-units, odd)
    float* ks = sm + 64*258;
    const int b = blockIdx.y, ch = blockIdx.x, tid = threadIdx.x;
    size_t qoff = ((size_t)512 + (size_t)b*64) * 65536 + (size_t)ch*256;  // q = kqv[1]
    size_t koff = ((size_t)b*64) * 65536 + (size_t)ch*256;                // k = kqv[0]
    for (int i = tid; i < 16384; i += 256) {
        int t = i >> 8, j = i & 255;
        qs[t*258 + j] = g_kqv[qoff + (size_t)t*65536 + j];
        ks[t*258 + j] = g_kqv[koff + (size_t)t*65536 + j];
    }
    __syncthreads();
    // lane mapping: t = tid>>2 (one q row per 4 lanes), sl = tid&3; this
    // thread covers s = sl + 4*j. Adjacent lanes hit adjacent ks rows ->
    // odd 8B row-stride 129 -> conflict-free LDS.64.
    int t = tid >> 2, sl = tid & 3;
    ull acc[16];
    #pragma unroll
    for (int j = 0; j < 16; j++) acc[j] = 0;
    const ull* qrow = (const ull*)(qs + t*258);
    for (int kk = 0; kk < 128; kk++) {
        ull q2 = qrow[kk];
        #pragma unroll
        for (int j = 0; j < 16; j++) {
            ull k2 = *(const ull*)(ks + (sl + 4*j)*258 + 2*kk);
            FMA2(acc[j], q2, k2);
        }
    }
    #pragma unroll
    for (int j = 0; j < 16; j++) {
        float2 r = upk(acc[j]);
        atomicAdd(&g_S[(b*64 + t)*64 + sl + 4*j], (r.x + r.y) * (1.f/65536.f));
    }
}

__global__ void k_softmax() {
    int b = blockIdx.x, t = threadIdx.x;           // 8 x 64
    float* row = &g_S[(b*64 + t)*64];
    float mx = -1e30f;
    for (int s = 0; s < 64; s++) mx = fmaxf(mx, row[s]);
    float sum = 0.f;
    for (int s = 0; s < 64; s++) { float v = expf(row[s] - mx); row[s] = v; sum += v; }
    float inv = 1.f / sum;
    for (int s = 0; s < 64; s++) row[s] *= inv;
}

// 2 px per thread, 32 t per z-half; attn weights duplicate-packed in smem
__global__ void k_attnv() {
    __shared__ ull As2[2048];                      // [32 t][64 s] pk(a,a)
    const int b = blockIdx.y, z = blockIdx.z, tid = threadIdx.x;
    const int p = blockIdx.x * 512 + tid * 2;
    for (int i = tid; i < 2048; i += 256) {
        float a = g_S[b*4096 + z*2048 + i];
        As2[i] = pk2(a, a);
    }
    __syncthreads();
    ull acc[32];
    #pragma unroll
    for (int t = 0; t < 32; t++) acc[t] = 0;
    size_t vbase = ((size_t)1024 + (size_t)b*64) * 65536 + p;   // v = kqv[2]
    for (int s = 0; s < 64; s++) {
        ull vv = *(const ull*)(g_kqv + vbase + (size_t)s*65536);
        #pragma unroll
        for (int t = 0; t < 32; t++) FMA2(acc[t], vv, As2[t*64 + s]);
    }
    size_t obase = (size_t)b * 4194304 + (size_t)z * 32 * 65536 + p;
    #pragma unroll
    for (int t = 0; t < 32; t++) {
        float2 r = upk(acc[t]);
        *(float2*)(g_att + obase + (size_t)t*65536) = r;
    }
}

// ---------------- InstanceNorm2d + exact GELU (in place) --------------------
__global__ void k_inorm() {
    __shared__ float w1s[8], w2s[8];
    float* ptr = g_att + (size_t)blockIdx.x * HW;
    const int tid = threadIdx.x;
    float s1 = 0.f, s2 = 0.f;
    for (int i = tid; i < HW; i += 256) { float v = ptr[i]; s1 += v; s2 += v*v; }
    for (int off = 16; off; off >>= 1) {
        s1 += __shfl_down_sync(0xffffffffu, s1, off);
        s2 += __shfl_down_sync(0xffffffffu, s2, off);
    }
    if ((tid & 31) == 0) { w1s[tid >> 5] = s1; w2s[tid >> 5] = s2; }
    __syncthreads();
    if (tid == 0) {
        float a = 0.f, c = 0.f;
        for (int i = 0; i < 8; i++) { a += w1s[i]; c += w2s[i]; }
        w1s[0] = a * (1.f/HW); w2s[0] = c * (1.f/HW);
    }
    __syncthreads();
    float mu = w1s[0];
    float inv = rsqrtf(w2s[0] - mu*mu + 1e-5f);
    for (int i = tid; i < HW; i += 256) {
        float v = (ptr[i] - mu) * inv;
        ptr[i] = v * normcdff(v);
    }
}

// ---------------- end spectral multiply -------------------------------------
__global__ void k_spec_end(const float* __restrict__ w1r, const float* __restrict__ w1i,
                           const float* __restrict__ w2r, const float* __restrict__ w2i) {
    const int m = threadIdx.x;                 // 512
    const int o0 = blockIdx.x * 2;             // 128 blocks
    bool top = m < 256;
    int mm = top ? m : (m - 256);
    const float* wr = top ? w1r : w2r;
    const float* wi = top ? w1i : w2i;
    float2 a0[8], a1[8];
    #pragma unroll
    for (int b = 0; b < 8; b++) { a0[b] = make_float2(0.f,0.f); a1[b] = make_float2(0.f,0.f); }
    for (int i = 0; i < 256; i++) {
        float wr0 = wr[((size_t)i*256 + o0    )*256 + mm];
        float wi0 = wi[((size_t)i*256 + o0    )*256 + mm];
        float wr1 = wr[((size_t)i*256 + o0 + 1)*256 + mm];
        float wi1 = wi[((size_t)i*256 + o0 + 1)*256 + mm];
        #pragma unroll
        for (int b = 0; b < 8; b++) {
            float2 xv = g_XF[((size_t)(b*256 + i)) * NMODE + m];
            a0[b].x += xv.x*wr0 - xv.y*wi0;  a0[b].y += xv.x*wi0 + xv.y*wr0;
            a1[b].x += xv.x*wr1 - xv.y*wi1;  a1[b].y += xv.x*wi1 + xv.y*wr1;
        }
    }
    #pragma unroll
    for (int b = 0; b < 8; b++) {
        g_EOF[((size_t)(b*256 + o0    )) * NMODE + m] = a0[b];
        g_EOF[((size_t)(b*256 + o0 + 1)) * NMODE + m] = a1[b];
    }
}

// ---------------- end inverse partial DFT -> d_out --------------------------
__global__ void k_idft_end(float* __restrict__ out) {
    __shared__ float2 OFs[512];
    __shared__ float2 U[2048];
    __shared__ float ct[128], st[128];
    const int tid = threadIdx.x;               // 256
    const int plane = blockIdx.x;              // 2048
    if (tid < 128) { float a = (float)tid * (PI2/128.f); ct[tid] = cosf(a); st[tid] = sinf(a); }
    for (int i = tid; i < 512; i += 256) OFs[i] = g_EOF[(size_t)plane*512 + i];
    __syncthreads();
    for (int e = tid; e < 2048; e += 256) {
        int h = e >> 4, m2 = e & 15;
        float ux = 0.f, uy = 0.f;
        #pragma unroll
        for (int m1i = 0; m1i < 32; m1i++) {
            int r = (m1i < 16) ? m1i : (m1i + 96);
            int idx = (r * h) & 127;
            float c = ct[idx], sn = st[idx];
            float2 X = OFs[m1i*16 + m2];
            ux += X.x*c  - X.y*sn;
            uy += X.x*sn + X.y*c;
        }
        float a = (m2 == 0) ? 1.f : 2.f;
        U[e] = make_float2(ux*a, uy*a);
    }
    __syncthreads();
    int w = tid & 127, h0 = (tid >> 7) * 64;
    ull tw2[16];
    #pragma unroll
    for (int m2 = 0; m2 < 16; m2++) {
        int idx = (m2*w) & 127;
        tw2[m2] = pk2(ct[idx], -st[idx]);
    }
    for (int h = h0; h < h0 + 64; h++) {
        const ull* Up = (const ull*)(U + (h << 4));
        ull a2 = 0;
        #pragma unroll
        for (int m2 = 0; m2 < 16; m2++) FMA2(a2, Up[m2], tw2[m2]);
        float2 r = upk(a2);
        out[(size_t)plane*HW + (h << 7) + w] = r.x + r.y;
    }
}

// ---------------- end pointwise skip GEMM (accumulates into d_out) ----------
static const int SM_ENDSK = 32*128*8 + 32*128*4;   // 49152 B

__global__ void k_endskip(const float* __restrict__ skip, float* __restrict__ out) {
    extern __shared__ __align__(16) unsigned char smraw[];
    ull*   Ssp = (ull*)smraw;                  // [32 k][128 o] pk(s,s)
    float* Gs  = (float*)(Ssp + 4096);         // [32 k][128 p]
    const int b = blockIdx.z, o0 = blockIdx.y * 128, p0 = blockIdx.x * 128;
    const int tid = threadIdx.x;
    const int oy = tid >> 4, px = tid & 15;
    ull acc[8][4];
    #pragma unroll
    for (int j = 0; j < 8; j++)
        #pragma unroll
        for (int jj = 0; jj < 4; jj++) acc[j][jj] = 0;

    for (int kc = 0; kc < 256; kc += 32) {
        for (int i = tid; i < 4096; i += 256) {
            int o = i & 127, k = i >> 7;
            float s = skip[(size_t)(o0 + o)*256 + kc + k];
            Ssp[k*128 + o] = pk2(s, s);
        }
        for (int i = tid; i < 4096; i += 256) {
            int c = i & 127, ir = i >> 7;
            Gs[ir*128 + c] = g_att[((size_t)b*256 + kc + ir) * HW + p0 + c];
        }
        __syncthreads();
        #pragma unroll 4
        for (int k = 0; k < 32; k++) {
            ull gv[4];
            const ull* gp = (const ull*)(Gs + k*128);
            #pragma unroll
            for (int jj = 0; jj < 4; jj++) gv[jj] = gp[px + 16*jj];
            #pragma unroll
            for (int j = 0; j < 8; j++) {
                ull sv = Ssp[k*128 + oy + 16*j];
                #pragma unroll
                for (int jj = 0; jj < 4; jj++) FMA2(acc[j][jj], gv[jj], sv);
            }
        }
        __syncthreads();
    }
    #pragma unroll
    for (int j = 0; j < 8; j++)
        #pragma unroll
        for (int jj = 0; jj < 4; jj++) {
            size_t oidx = ((size_t)b*256 + o0 + oy + 16*j) * HW + p0 + 2*px + 32*jj;
            float2 r = upk(acc[j][jj]);
            float2* op = (float2*)(out + oidx);
            float2 cur = *op;
            cur.x += r.x; cur.y += r.y;
            *op = cur;
        }
}

// ---------------- launch -----------------------------------------------------
extern "C" void kernel_launch(void* const* d_in, const int* in_sizes, int n_in,
                              void* d_out, int out_size) {
    const float* x        = (const float*)d_in[0];
    const float* kqv_w1r  = (const float*)d_in[1];
    const float* kqv_w1i  = (const float*)d_in[2];
    const float* kqv_w2r  = (const float*)d_in[3];
    const float* kqv_w2i  = (const float*)d_in[4];
    const float* kqv_skip = (const float*)d_in[5];
    const float* end_w1r  = (const float*)d_in[6];
    const float* end_w1i  = (const float*)d_in[7];
    const float* end_w2r  = (const float*)d_in[8];
    const float* end_w2i  = (const float*)d_in[9];
    const float* end_skip = (const float*)d_in[10];
    float* out = (float*)d_out;

    cudaFuncSetAttribute(k_fwd_dft,  cudaFuncAttributeMaxDynamicSharedMemorySize, SM_FWD);
    cudaFuncSetAttribute(k_idft_kqv, cudaFuncAttributeMaxDynamicSharedMemorySize, SM_IDFTK);
    cudaFuncSetAttribute(k_scores,   cudaFuncAttributeMaxDynamicSharedMemorySize, SM_SCORES);
    cudaFuncSetAttribute(k_endskip,  cudaFuncAttributeMaxDynamicSharedMemorySize, SM_ENDSK);

    float2* gXF;  cudaGetSymbolAddress((void**)&gXF,  g_XF);
    float*  gAtt; cudaGetSymbolAddress((void**)&gAtt, g_att);

    // stage 1
    k_fwd_dft<<<2048, 256, SM_FWD>>>(x, gXF);
    k_spec_kqv<<<1536, 512>>>(kqv_w1r, kqv_w1i, kqv_w2r, kqv_w2i);
    k_idft_kqv<<<1536, 256, SM_IDFTK>>>(x, kqv_skip);

    // attention over tokens
    k_zero<<<64, 256>>>(0);
    k_zero<<<64, 256>>>(16384);
    k_scores<<<dim3(256, 8), 256, SM_SCORES>>>();
    k_softmax<<<8, 64>>>();
    k_attnv<<<dim3(128, 8, 2), 256>>>();

    // instance norm + gelu
    k_inorm<<<2048, 256>>>();

    // stage 2: end FNO block
    k_fwd_dft<<<2048, 256, SM_FWD>>>(gAtt, gXF);
    k_spec_end<<<128, 512>>>(end_w1r, end_w1i, end_w2r, end_w2i);
    k_idft_end<<<2048, 256>>>(out);
    k_endskip<<<dim3(128, 2, 8), 256, SM_ENDSK>>>(end_skip, out);   // <- smem arg was missing (the R4/R5 IMA)
}

// round 10
// speedup vs baseline: 1.2637x; 1.0521x over previous
#include <cuda_runtime.h>
#include <math.h>

#define HW    16384
#define NMODE 512
#define PI2   6.28318530717958647692f

typedef unsigned long long ull;

// packed fp32x2 helpers (sm_100+: FFMA2)
__device__ __forceinline__ ull pk2(float a, float b) {
    ull r; asm("mov.b64 %0, {%1,%2};" : "=l"(r) : "f"(a), "f"(b)); return r;
}
__device__ __forceinline__ float2 upk(ull v) {
    float2 r; asm("mov.b64 {%0,%1}, %2;" : "=f"(r.x), "=f"(r.y) : "l"(v)); return r;
}
#define FMA2(d, a, b) asm("fma.rn.f32x2 %0, %1, %2, %0;" : "+l"(d) : "l"(a), "l"(b))

// ---- scratch (device globals; 16B-aligned for 8B vector accesses) ----
__device__ __align__(16) float2 g_XF [2048 * NMODE];
__device__ __align__(16) float2 g_OF [3 * 2048 * NMODE];
__device__ __align__(16) float  g_kqv[100663296];     // [3][512][4][16384]
__device__ __align__(16) float  g_S  [32768];         // [8][64][64]
__device__ __align__(16) float  g_att[33554432];      // [8][256][16384]
__device__ __align__(16) float2 g_EOF[2048 * NMODE];

// ---------------- forward partial DFT: 128x128 plane -> 32x16 modes ----------
// smem: xs[128][129] f | T1[128][16] f2 | tw2[16][128] ull | ct[128] | st[128]
static const int SM_FWD = 128*129*4 + 128*16*8 + 16*128*8 + 256*4;   // 99840 B

__global__ void k_fwd_dft(const float* __restrict__ src, float2* __restrict__ dst) {
    extern __shared__ float sm[];
    float*  xs  = sm;                                // [128][129]
    float2* T1  = (float2*)(sm + 128*129);           // [128][16]
    ull*    tw2 = (ull*)(T1 + 128*16);               // [16][128] (c, -s)
    float*  ct  = (float*)(tw2 + 2048);
    float*  st  = ct + 128;
    const int tid = threadIdx.x;                     // 256
    const float* x = src + (size_t)blockIdx.x * HW;

    if (tid < 128) { float a = (float)tid * (PI2/128.f); ct[tid] = cosf(a); st[tid] = sinf(a); }
    for (int i = tid; i < HW; i += 256) xs[(i >> 7)*129 + (i & 127)] = x[i];
    __syncthreads();

    for (int i = tid; i < 2048; i += 256) {
        int idx = ((i >> 7) * (i & 127)) & 127;
        tw2[i] = pk2(ct[idx], -st[idx]);
    }
    __syncthreads();

    {   // phase 1: T1[h][m2] = sum_w x[h][w] e^{-2pi i m2 w/128}  (FMA2)
        int h = tid >> 1, m2b = (tid & 1) * 8;
        ull acc[8];
        #pragma unroll
        for (int j = 0; j < 8; j++) acc[j] = 0;
        const float* xr = xs + h*129;
        for (int w = 0; w < 128; w++) {
            ull xv2 = pk2(xr[w], xr[w]);
            #pragma unroll
            for (int j = 0; j < 8; j++)
                FMA2(acc[j], xv2, tw2[(m2b + j)*128 + w]);
        }
        #pragma unroll
        for (int j = 0; j < 8; j++) *(ull*)&T1[h*16 + m2b + j] = acc[j];
    }
    __syncthreads();

    // phase 2: fold h with row-mode twiddles (rows 0..15 and 112..127)
    #pragma unroll
    for (int rep = 0; rep < 2; rep++) {
        int om  = tid*2 + rep;
        int m1i = om >> 4, m2 = om & 15;
        int r   = (m1i < 16) ? m1i : (m1i + 96);
        float sx = 0.f, sy = 0.f;
        for (int h = 0; h < 128; h++) {
            int idx = (r * h) & 127;
            float c = ct[idx], s = st[idx];
            float2 t = T1[h*16 + m2];
            sx += t.x*c + t.y*s;
            sy += t.y*c - t.x*s;
        }
        dst[(size_t)blockIdx.x * NMODE + om] = make_float2(sx*(1.f/16384.f), sy*(1.f/16384.f));
    }
}

// ---------------- kqv spectral multiply ----------------
__global__ void k_spec_kqv(const float* __restrict__ w1r, const float* __restrict__ w1i,
                           const float* __restrict__ w2r, const float* __restrict__ w2i) {
    int s = blockIdx.x >> 9, n = blockIdx.x & 511;
    int m = threadIdx.x;                 // 512
    bool top = m < 256;
    int mm = top ? m : (m - 256);
    const float* wr = top ? w1r : w2r;
    const float* wi = top ? w1i : w2i;

    float2 xv[4];
    #pragma unroll
    for (int i = 0; i < 4; i++) xv[i] = g_XF[(size_t)(n*4 + i) * NMODE + m];

    #pragma unroll
    for (int o = 0; o < 4; o++) {
        float ax = 0.f, ay = 0.f;
        #pragma unroll
        for (int i = 0; i < 4; i++) {
            float a = wr[s*4096 + (i*4 + o)*256 + mm];
            float b = wi[s*4096 + (i*4 + o)*256 + mm];
            ax += xv[i].x*a - xv[i].y*b;
            ay += xv[i].x*b + xv[i].y*a;
        }
        g_OF[((size_t)(s*512 + n)*4 + o) * NMODE + m] = make_float2(ax, ay);
    }
}

// ---------------- kqv inverse partial DFT + pointwise skip -------------------
// smem: OFs[2048] f2 | U[8192] f2 | cc2[128] ull | ss2[128] ull | ct | st | sk
static const int SM_IDFTK = 2048*8 + 8192*8 + 128*8*2 + 256*4 + 16*4;   // 85056 B

__global__ void k_idft_kqv(const float* __restrict__ x, const float* __restrict__ skip) {
    extern __shared__ float sm[];
    float2* OFs = (float2*)sm;                 // [4][32][16]
    float2* U   = OFs + 2048;                  // [4][128][16]
    ull*    cc2 = (ull*)(U + 8192);            // (c,c)
    ull*    ss2 = cc2 + 128;                   // (s,s)
    float*  ct  = (float*)(ss2 + 128);
    float*  st  = ct + 128;
    float*  sk  = st + 128;                    // [4][4] (o,i)
    const int tid = threadIdx.x;               // 256
    const int s = blockIdx.x >> 9, n = blockIdx.x & 511;

    if (tid < 128) {
        float a = (float)tid * (PI2/128.f);
        float c = cosf(a), sn = sinf(a);
        ct[tid] = c; st[tid] = sn;
        cc2[tid] = pk2(c, c); ss2[tid] = pk2(sn, sn);
    }
    if (tid < 16)  sk[tid] = skip[s*16 + tid];
    for (int i = tid; i < 2048; i += 256)
        OFs[i] = g_OF[((size_t)(s*512 + n)*4) * NMODE + i];
    __syncthreads();

    // phase 1 (register-tiled, FMA2): U[o][h][m2] = a(m2)*sum_m1 OF[o][m1][m2] e^{+i r h}
    #pragma unroll
    for (int k = 0; k < 4; k++) {
        const int o  = k;                      // u = k*256+tid -> o = k
        const int h  = tid >> 1;
        const int jh = (tid & 1) * 8;
        ull ar[8], ai[8];
        #pragma unroll
        for (int j = 0; j < 8; j++) { ar[j] = 0; ai[j] = 0; }
        const ull* Xb = (const ull*)OFs + o*512 + jh;
        #pragma unroll 8
        for (int m1i = 0; m1i < 32; m1i++) {
            int r = (m1i < 16) ? m1i : (m1i + 96);
            int idx = (r * h) & 127;
            ull cc = cc2[idx], ss = ss2[idx];
            #pragma unroll
            for (int j = 0; j < 8; j++) {
                ull X = Xb[m1i*16 + j];
                FMA2(ar[j], X, cc);
                FMA2(ai[j], X, ss);
            }
        }
        #pragma unroll
        for (int j = 0; j < 8; j++) {
            float2 r2 = upk(ar[j]), i2 = upk(ai[j]);
            float ux = r2.x - i2.y;            // Re: Xx c - Xy s
            float uy = i2.x + r2.y;            // Im: Xx s + Xy c
            float a = ((jh + j) == 0) ? 1.f : 2.f;
            U[(o << 11) + (h << 4) + jh + j] = make_float2(ux*a, uy*a);
        }
    }
    __syncthreads();

    // phase 2: expand over m2 (Re part) via packed FMA2 + skip
    int w = tid & 127, o0 = (tid >> 7) * 2;
    ull tw2[16];
    #pragma unroll
    for (int m2 = 0; m2 < 16; m2++) {
        int idx = (m2*w) & 127;
        tw2[m2] = pk2(ct[idx], -st[idx]);
    }
    float s00 = sk[o0*4+0], s01 = sk[o0*4+1], s02 = sk[o0*4+2], s03 = sk[o0*4+3];
    float s10 = sk[o0*4+4], s11 = sk[o0*4+5], s12 = sk[o0*4+6], s13 = sk[o0*4+7];
    size_t outbase = ((size_t)(s*512 + n)*4 + o0) * HW;
    size_t xbase   = (size_t)n * 4 * HW;

    for (int h = 0; h < 128; h++) {
        const ull* U0 = (const ull*)(U + (o0 << 11) + (h << 4));
        const ull* U1 = (const ull*)(U + ((o0+1) << 11) + (h << 4));
        ull a0 = 0, a1 = 0;
        #pragma unroll
        for (int m2 = 0; m2 < 16; m2++) {
            FMA2(a0, U0[m2], tw2[m2]);
            FMA2(a1, U1[m2], tw2[m2]);
        }
        float2 r0 = upk(a0), r1 = upk(a1);
        float v0 = r0.x + r0.y, v1 = r1.x + r1.y;
        int p = (h << 7) + w;
        float x0 = x[xbase + p],        x1 = x[xbase + HW + p];
        float x2 = x[xbase + 2*HW + p], x3 = x[xbase + 3*HW + p];
        v0 += s00*x0 + s01*x1 + s02*x2 + s03*x3;
        v1 += s10*x0 + s11*x1 + s12*x2 + s13*x3;
        g_kqv[outbase + p]      = v0;
        g_kqv[outbase + HW + p] = v1;
    }
}

// ---------------- attention --------------------------------------------------
__global__ void k_zero(int off) {
    g_S[off + blockIdx.x*256 + threadIdx.x] = 0.f;
}

static const int SM_SCORES = 2*64*258*4;   // 132096 B

__global__ void k_scores() {
    extern __shared__ float sm[];
    float* qs = sm;             // [64][258]  (row stride 258 floats = 129 8B-units, odd)
    float* ks = sm + 64*258;
    const int b = blockIdx.y, ch = blockIdx.x, tid = threadIdx.x;
    size_t qoff = ((size_t)512 + (size_t)b*64) * 65536 + (size_t)ch*256;  // q = kqv[1]
    size_t koff = ((size_t)b*64) * 65536 + (size_t)ch*256;                // k = kqv[0]
    for (int i = tid; i < 16384; i += 256) {
        int t = i >> 8, j = i & 255;
        qs[t*258 + j] = g_kqv[qoff + (size_t)t*65536 + j];
        ks[t*258 + j] = g_kqv[koff + (size_t)t*65536 + j];
    }
    __syncthreads();
    int t = tid >> 2, sl = tid & 3;
    ull acc[16];
    #pragma unroll
    for (int j = 0; j < 16; j++) acc[j] = 0;
    const ull* qrow = (const ull*)(qs + t*258);
    for (int kk = 0; kk < 128; kk++) {
        ull q2 = qrow[kk];
        #pragma unroll
        for (int j = 0; j < 16; j++) {
            ull k2 = *(const ull*)(ks + (sl + 4*j)*258 + 2*kk);
            FMA2(acc[j], q2, k2);
        }
    }
    #pragma unroll
    for (int j = 0; j < 16; j++) {
        float2 r = upk(acc[j]);
        atomicAdd(&g_S[(b*64 + t)*64 + sl + 4*j], (r.x + r.y) * (1.f/65536.f));
    }
}

__global__ void k_softmax() {
    int b = blockIdx.x, t = threadIdx.x;           // 8 x 64
    float* row = &g_S[(b*64 + t)*64];
    float mx = -1e30f;
    for (int s = 0; s < 64; s++) mx = fmaxf(mx, row[s]);
    float sum = 0.f;
    for (int s = 0; s < 64; s++) { float v = expf(row[s] - mx); row[s] = v; sum += v; }
    float inv = 1.f / sum;
    for (int s = 0; s < 64; s++) row[s] *= inv;
}

// 2 px per thread, 32 t per z-half; attn weights duplicate-packed in smem
__global__ void k_attnv() {
    __shared__ ull As2[2048];                      // [32 t][64 s] pk(a,a)
    const int b = blockIdx.y, z = blockIdx.z, tid = threadIdx.x;
    const int p = blockIdx.x * 512 + tid * 2;
    for (int i = tid; i < 2048; i += 256) {
        float a = g_S[b*4096 + z*2048 + i];
        As2[i] = pk2(a, a);
    }
    __syncthreads();
    ull acc[32];
    #pragma unroll
    for (int t = 0; t < 32; t++) acc[t] = 0;
    size_t vbase = ((size_t)1024 + (size_t)b*64) * 65536 + p;   // v = kqv[2]
    for (int s = 0; s < 64; s++) {
        ull vv = *(const ull*)(g_kqv + vbase + (size_t)s*65536);
        #pragma unroll
        for (int t = 0; t < 32; t++) FMA2(acc[t], vv, As2[t*64 + s]);
    }
    size_t obase = (size_t)b * 4194304 + (size_t)z * 32 * 65536 + p;
    #pragma unroll
    for (int t = 0; t < 32; t++) {
        float2 r = upk(acc[t]);
        *(float2*)(g_att + obase + (size_t)t*65536) = r;
    }
}

// ---------------- InstanceNorm2d + exact GELU (in place) --------------------
__global__ void k_inorm() {
    __shared__ float w1s[8], w2s[8];
    float* ptr = g_att + (size_t)blockIdx.x * HW;
    const int tid = threadIdx.x;
    float s1 = 0.f, s2 = 0.f;
    for (int i = tid; i < HW; i += 256) { float v = ptr[i]; s1 += v; s2 += v*v; }
    for (int off = 16; off; off >>= 1) {
        s1 += __shfl_down_sync(0xffffffffu, s1, off);
        s2 += __shfl_down_sync(0xffffffffu, s2, off);
    }
    if ((tid & 31) == 0) { w1s[tid >> 5] = s1; w2s[tid >> 5] = s2; }
    __syncthreads();
    if (tid == 0) {
        float a = 0.f, c = 0.f;
        for (int i = 0; i < 8; i++) { a += w1s[i]; c += w2s[i]; }
        w1s[0] = a * (1.f/HW); w2s[0] = c * (1.f/HW);
    }
    __syncthreads();
    float mu = w1s[0];
    float inv = rsqrtf(w2s[0] - mu*mu + 1e-5f);
    for (int i = tid; i < HW; i += 256) {
        float v = (ptr[i] - mu) * inv;
        ptr[i] = v * normcdff(v);
    }
}

// ---------------- end spectral multiply (FMA2 split-accumulator) ------------
__global__ void k_spec_end(const float* __restrict__ w1r, const float* __restrict__ w1i,
                           const float* __restrict__ w2r, const float* __restrict__ w2i) {
    const int m = threadIdx.x;                 // 512
    const int o0 = blockIdx.x * 2;             // 128 blocks
    bool top = m < 256;
    int mm = top ? m : (m - 256);
    const float* wr = top ? w1r : w2r;
    const float* wi = top ? w1i : w2i;
    ull r0[8], i0[8], r1[8], i1[8];
    #pragma unroll
    for (int b = 0; b < 8; b++) { r0[b]=0; i0[b]=0; r1[b]=0; i1[b]=0; }
    const ull* XF = (const ull*)g_XF + m;
    for (int i = 0; i < 256; i++) {
        float wr0 = wr[((size_t)i*256 + o0    )*256 + mm];
        float wi0 = wi[((size_t)i*256 + o0    )*256 + mm];
        float wr1 = wr[((size_t)i*256 + o0 + 1)*256 + mm];
        float wi1 = wi[((size_t)i*256 + o0 + 1)*256 + mm];
        ull wr02 = pk2(wr0, wr0), wi02 = pk2(wi0, wi0);
        ull wr12 = pk2(wr1, wr1), wi12 = pk2(wi1, wi1);
        #pragma unroll
        for (int b = 0; b < 8; b++) {
            ull X = XF[(size_t)(b*256 + i) * NMODE];
            FMA2(r0[b], X, wr02);  FMA2(i0[b], X, wi02);
            FMA2(r1[b], X, wr12);  FMA2(i1[b], X, wi12);
        }
    }
    #pragma unroll
    for (int b = 0; b < 8; b++) {
        float2 ar = upk(r0[b]), ai = upk(i0[b]);
        g_EOF[((size_t)(b*256 + o0    )) * NMODE + m] = make_float2(ar.x - ai.y, ai.x + ar.y);
        float2 br = upk(r1[b]), bi = upk(i1[b]);
        g_EOF[((size_t)(b*256 + o0 + 1)) * NMODE + m] = make_float2(br.x - bi.y, bi.x + br.y);
    }
}

// ---------------- end inverse partial DFT -> d_out --------------------------
__global__ void k_idft_end(float* __restrict__ out) {
    __shared__ float2 OFs[512];
    __shared__ float2 U[2048];
    __shared__ ull cc2[128], ss2[128];
    __shared__ float ct[128], st[128];
    const int tid = threadIdx.x;               // 256
    const int plane = blockIdx.x;              // 2048
    if (tid < 128) {
        float a = (float)tid * (PI2/128.f);
        float c = cosf(a), sn = sinf(a);
        ct[tid] = c; st[tid] = sn;
        cc2[tid] = pk2(c, c); ss2[tid] = pk2(sn, sn);
    }
    for (int i = tid; i < 512; i += 256) OFs[i] = g_EOF[(size_t)plane*512 + i];
    __syncthreads();

    {   // phase 1 (register-tiled FMA2): one (h, jh) per thread
        const int h  = tid >> 1;
        const int jh = (tid & 1) * 8;
        ull ar[8], ai[8];
        #pragma unroll
        for (int j = 0; j < 8; j++) { ar[j] = 0; ai[j] = 0; }
        const ull* Xb = (const ull*)OFs + jh;
        #pragma unroll 8
        for (int m1i = 0; m1i < 32; m1i++) {
            int r = (m1i < 16) ? m1i : (m1i + 96);
            int idx = (r * h) & 127;
            ull cc = cc2[idx], ss = ss2[idx];
            #pragma unroll
            for (int j = 0; j < 8; j++) {
                ull X = Xb[m1i*16 + j];
                FMA2(ar[j], X, cc);
                FMA2(ai[j], X, ss);
            }
        }
        #pragma unroll
        for (int j = 0; j < 8; j++) {
            float2 r2 = upk(ar[j]), i2 = upk(ai[j]);
            float ux = r2.x - i2.y;
            float uy = i2.x + r2.y;
            float a = ((jh + j) == 0) ? 1.f : 2.f;
            U[(h << 4) + jh + j] = make_float2(ux*a, uy*a);
        }
    }
    __syncthreads();

    int w = tid & 127, h0 = (tid >> 7) * 64;
    ull tw2[16];
    #pragma unroll
    for (int m2 = 0; m2 < 16; m2++) {
        int idx = (m2*w) & 127;
        tw2[m2] = pk2(ct[idx], -st[idx]);
    }
    for (int h = h0; h < h0 + 64; h++) {
        const ull* Up = (const ull*)(U + (h << 4));
        ull a2 = 0;
        #pragma unroll
        for (int m2 = 0; m2 < 16; m2++) FMA2(a2, Up[m2], tw2[m2]);
        float2 r = upk(a2);
        out[(size_t)plane*HW + (h << 7) + w] = r.x + r.y;
    }
}

// ---------------- end pointwise skip GEMM (accumulates into d_out) ----------
static const int SM_ENDSK = 32*128*8 + 32*128*4;   // 49152 B

__global__ void k_endskip(const float* __restrict__ skip, float* __restrict__ out) {
    extern __shared__ __align__(16) unsigned char smraw[];
    ull*   Ssp = (ull*)smraw;                  // [32 k][128 o] pk(s,s)
    float* Gs  = (float*)(Ssp + 4096);         // [32 k][128 p]
    const int b = blockIdx.z, o0 = blockIdx.y * 128, p0 = blockIdx.x * 128;
    const int tid = threadIdx.x;
    const int oy = tid >> 4, px = tid & 15;
    ull acc[8][4];
    #pragma unroll
    for (int j = 0; j < 8; j++)
        #pragma unroll
        for (int jj = 0; jj < 4; jj++) acc[j][jj] = 0;

    for (int kc = 0; kc < 256; kc += 32) {
        for (int i = tid; i < 4096; i += 256) {
            int o = i & 127, k = i >> 7;
            float s = skip[(size_t)(o0 + o)*256 + kc + k];
            Ssp[k*128 + o] = pk2(s, s);
        }
        for (int i = tid; i < 4096; i += 256) {
            int c = i & 127, ir = i >> 7;
            Gs[ir*128 + c] = g_att[((size_t)b*256 + kc + ir) * HW + p0 + c];
        }
        __syncthreads();
        #pragma unroll 4
        for (int k = 0; k < 32; k++) {
            ull gv[4];
            const ull* gp = (const ull*)(Gs + k*128);
            #pragma unroll
            for (int jj = 0; jj < 4; jj++) gv[jj] = gp[px + 16*jj];
            #pragma unroll
            for (int j = 0; j < 8; j++) {
                ull sv = Ssp[k*128 + oy + 16*j];
                #pragma unroll
                for (int jj = 0; jj < 4; jj++) FMA2(acc[j][jj], gv[jj], sv);
            }
        }
        __syncthreads();
    }
    #pragma unroll
    for (int j = 0; j < 8; j++)
        #pragma unroll
        for (int jj = 0; jj < 4; jj++) {
            size_t oidx = ((size_t)b*256 + o0 + oy + 16*j) * HW + p0 + 2*px + 32*jj;
            float2 r = upk(acc[j][jj]);
            float2* op = (float2*)(out + oidx);
            float2 cur = *op;
            cur.x += r.x; cur.y += r.y;
            *op = cur;
        }
}

// ---------------- launch -----------------------------------------------------
extern "C" void kernel_launch(void* const* d_in, const int* in_sizes, int n_in,
                              void* d_out, int out_size) {
    const float* x        = (const float*)d_in[0];
    const float* kqv_w1r  = (const float*)d_in[1];
    const float* kqv_w1i  = (const float*)d_in[2];
    const float* kqv_w2r  = (const float*)d_in[3];
    const float* kqv_w2i  = (const float*)d_in[4];
    const float* kqv_skip = (const float*)d_in[5];
    const float* end_w1r  = (const float*)d_in[6];
    const float* end_w1i  = (const float*)d_in[7];
    const float* end_w2r  = (const float*)d_in[8];
    const float* end_w2i  = (const float*)d_in[9];
    const float* end_skip = (const float*)d_in[10];
    float* out = (float*)d_out;

    cudaFuncSetAttribute(k_fwd_dft,  cudaFuncAttributeMaxDynamicSharedMemorySize, SM_FWD);
    cudaFuncSetAttribute(k_idft_kqv, cudaFuncAttributeMaxDynamicSharedMemorySize, SM_IDFTK);
    cudaFuncSetAttribute(k_scores,   cudaFuncAttributeMaxDynamicSharedMemorySize, SM_SCORES);
    cudaFuncSetAttribute(k_endskip,  cudaFuncAttributeMaxDynamicSharedMemorySize, SM_ENDSK);

    float2* gXF;  cudaGetSymbolAddress((void**)&gXF,  g_XF);
    float*  gAtt; cudaGetSymbolAddress((void**)&gAtt, g_att);

    // zeros first (keeps ncu's -s 5 window on heavy kernels)
    k_zero<<<64, 256>>>(0);                                         // 1
    k_zero<<<64, 256>>>(16384);                                     // 2

    // stage 1
    k_fwd_dft<<<2048, 256, SM_FWD>>>(x, gXF);                       // 3
    k_spec_kqv<<<1536, 512>>>(kqv_w1r, kqv_w1i, kqv_w2r, kqv_w2i);  // 4
    k_idft_kqv<<<1536, 256, SM_IDFTK>>>(x, kqv_skip);               // 5

    // attention over tokens
    k_scores<<<dim3(256, 8), 256, SM_SCORES>>>();                   // 6
    k_softmax<<<8, 64>>>();
    k_attnv<<<dim3(128, 8, 2), 256>>>();

    // instance norm + gelu
    k_inorm<<<2048, 256>>>();

    // stage 2: end FNO block
    k_fwd_dft<<<2048, 256, SM_FWD>>>(gAtt, gXF);
    k_spec_end<<<128, 512>>>(end_w1r, end_w1i, end_w2r, end_w2i);
    k_idft_end<<<2048, 256>>>(out);
    k_endskip<<<dim3(128, 2, 8), 256, SM_ENDSK>>>(end_skip, out);
}

// round 13
// speedup vs baseline: 1.3979x; 1.1061x over previous
#include <cuda_runtime.h>
#include <math.h>

#define HW    16384
#define NMODE 512
#define PI2   6.28318530717958647692f

typedef unsigned long long ull;

// packed fp32x2 helpers (sm_100+: FFMA2)
__device__ __forceinline__ ull pk2(float a, float b) {
    ull r; asm("mov.b64 %0, {%1,%2};" : "=l"(r) : "f"(a), "f"(b)); return r;
}
__device__ __forceinline__ float2 upk(ull v) {
    float2 r; asm("mov.b64 {%0,%1}, %2;" : "=f"(r.x), "=f"(r.y) : "l"(v)); return r;
}
#define FMA2(d, a, b) asm("fma.rn.f32x2 %0, %1, %2, %0;" : "+l"(d) : "l"(a), "l"(b))

// ---- scratch (device globals; 16B-aligned for 8B vector accesses) ----
__device__ __align__(16) float2 g_XF [2048 * NMODE];
__device__ __align__(16) float2 g_OF [3 * 2048 * NMODE];
__device__ __align__(16) float  g_kqv[100663296];     // [3][512][4][16384]
__device__ __align__(16) float  g_S  [32768];         // [8][64][64]
__device__ __align__(16) float  g_att[33554432];      // [8][256][16384]
__device__ __align__(16) float2 g_EOF[2048 * NMODE];

// ---------------- forward partial DFT: 128x128 plane -> 32x16 modes ----------
// layout (bytes): tw2[2048]u @0 | cc2[128]u @16384 | ss2[128]u @17408 |
//                 xs[128*129]f @18432 | T1[128*16]f2 @84480 | ct,st @100864
static const int SM_FWD = 101888;

__global__ void k_fwd_dft(const float* __restrict__ src, float2* __restrict__ dst) {
    extern __shared__ __align__(16) unsigned char smraw[];
    ull*    tw2 = (ull*)smraw;                       // [16][128] (c, -s)
    ull*    cc2 = tw2 + 2048;                        // (c,c)
    ull*    ss2 = cc2 + 128;                         // (s,s)
    float*  xs  = (float*)(smraw + 18432);           // [128][129]
    float2* T1  = (float2*)(smraw + 84480);          // [128][16]
    float*  ct  = (float*)(smraw + 100864);
    float*  st  = ct + 128;
    const int tid = threadIdx.x;                     // 256
    const float* x = src + (size_t)blockIdx.x * HW;

    if (tid < 128) {
        float a = (float)tid * (PI2/128.f);
        float c = cosf(a), s = sinf(a);
        ct[tid] = c; st[tid] = s;
        cc2[tid] = pk2(c, c); ss2[tid] = pk2(s, s);
    }
    for (int i = tid; i < HW; i += 256) xs[(i >> 7)*129 + (i & 127)] = x[i];
    __syncthreads();

    for (int i = tid; i < 2048; i += 256) {
        int idx = ((i >> 7) * (i & 127)) & 127;
        tw2[i] = pk2(ct[idx], -st[idx]);
    }
    __syncthreads();

    {   // phase 1: T1[h][m2] = sum_w x[h][w] e^{-2pi i m2 w/128}  (FMA2)
        int h = tid >> 1, m2b = (tid & 1) * 8;
        ull acc[8];
        #pragma unroll
        for (int j = 0; j < 8; j++) acc[j] = 0;
        const float* xr = xs + h*129;
        for (int w = 0; w < 128; w++) {
            ull xv2 = pk2(xr[w], xr[w]);
            #pragma unroll
            for (int j = 0; j < 8; j++)
                FMA2(acc[j], xv2, tw2[(m2b + j)*128 + w]);
        }
        #pragma unroll
        for (int j = 0; j < 8; j++) *(ull*)&T1[h*16 + m2b + j] = acc[j];
    }
    __syncthreads();

    // phase 2 (FMA2 split-accumulator): fold h with row-mode twiddles
    #pragma unroll
    for (int rep = 0; rep < 2; rep++) {
        int om  = tid + rep*256;
        int m1i = om >> 4, m2 = om & 15;
        int r   = (m1i < 16) ? m1i : (m1i + 96);
        ull ar = 0, ai = 0;
        const ull* T1u = (const ull*)T1 + m2;
        #pragma unroll 4
        for (int h = 0; h < 128; h++) {
            int idx = (r * h) & 127;
            ull t = T1u[h*16];
            FMA2(ar, t, cc2[idx]);     // (tx c, ty c)
            FMA2(ai, t, ss2[idx]);     // (tx s, ty s)
        }
        float2 a = upk(ar), b = upk(ai);
        // sx = sum tx c + ty s ; sy = sum ty c - tx s
        dst[(size_t)blockIdx.x * NMODE + om] =
            make_float2((a.x + b.y)*(1.f/16384.f), (a.y - b.x)*(1.f/16384.f));
    }
}

// ---------------- kqv spectral multiply ----------------
__global__ void k_spec_kqv(const float* __restrict__ w1r, const float* __restrict__ w1i,
                           const float* __restrict__ w2r, const float* __restrict__ w2i) {
    int s = blockIdx.x >> 9, n = blockIdx.x & 511;
    int m = threadIdx.x;                 // 512
    bool top = m < 256;
    int mm = top ? m : (m - 256);
    const float* wr = top ? w1r : w2r;
    const float* wi = top ? w1i : w2i;

    float2 xv[4];
    #pragma unroll
    for (int i = 0; i < 4; i++) xv[i] = g_XF[(size_t)(n*4 + i) * NMODE + m];

    #pragma unroll
    for (int o = 0; o < 4; o++) {
        float ax = 0.f, ay = 0.f;
        #pragma unroll
        for (int i = 0; i < 4; i++) {
            float a = wr[s*4096 + (i*4 + o)*256 + mm];
            float b = wi[s*4096 + (i*4 + o)*256 + mm];
            ax += xv[i].x*a - xv[i].y*b;
            ay += xv[i].x*b + xv[i].y*a;
        }
        g_OF[((size_t)(s*512 + n)*4 + o) * NMODE + m] = make_float2(ax, ay);
    }
}

// ---------------- kqv inverse partial DFT + pointwise skip -------------------
static const int SM_IDFTK = 2048*8 + 8192*8 + 128*8*2 + 256*4 + 16*4;   // 85056 B

__global__ void k_idft_kqv(const float* __restrict__ x, const float* __restrict__ skip) {
    extern __shared__ float sm[];
    float2* OFs = (float2*)sm;                 // [4][32][16]
    float2* U   = OFs + 2048;                  // [4][128][16]
    ull*    cc2 = (ull*)(U + 8192);            // (c,c)
    ull*    ss2 = cc2 + 128;                   // (s,s)
    float*  ct  = (float*)(ss2 + 128);
    float*  st  = ct + 128;
    float*  sk  = st + 128;                    // [4][4] (o,i)
    const int tid = threadIdx.x;               // 256
    const int s = blockIdx.x >> 9, n = blockIdx.x & 511;

    if (tid < 128) {
        float a = (float)tid * (PI2/128.f);
        float c = cosf(a), sn = sinf(a);
        ct[tid] = c; st[tid] = sn;
        cc2[tid] = pk2(c, c); ss2[tid] = pk2(sn, sn);
    }
    if (tid < 16)  sk[tid] = skip[s*16 + tid];
    for (int i = tid; i < 2048; i += 256)
        OFs[i] = g_OF[((size_t)(s*512 + n)*4) * NMODE + i];
    __syncthreads();

    // phase 1 (register-tiled, FMA2)
    #pragma unroll
    for (int k = 0; k < 4; k++) {
        const int o  = k;
        const int h  = tid >> 1;
        const int jh = (tid & 1) * 8;
        ull ar[8], ai[8];
        #pragma unroll
        for (int j = 0; j < 8; j++) { ar[j] = 0; ai[j] = 0; }
        const ull* Xb = (const ull*)OFs + o*512 + jh;
        #pragma unroll 8
        for (int m1i = 0; m1i < 32; m1i++) {
            int r = (m1i < 16) ? m1i : (m1i + 96);
            int idx = (r * h) & 127;
            ull cc = cc2[idx], ss = ss2[idx];
            #pragma unroll
            for (int j = 0; j < 8; j++) {
                ull X = Xb[m1i*16 + j];
                FMA2(ar[j], X, cc);
                FMA2(ai[j], X, ss);
            }
        }
        #pragma unroll
        for (int j = 0; j < 8; j++) {
            float2 r2 = upk(ar[j]), i2 = upk(ai[j]);
            float ux = r2.x - i2.y;
            float uy = i2.x + r2.y;
            float a = ((jh + j) == 0) ? 1.f : 2.f;
            U[(o << 11) + (h << 4) + jh + j] = make_float2(ux*a, uy*a);
        }
    }
    __syncthreads();

    // phase 2: expand over m2 (Re part) via packed FMA2 + skip
    int w = tid & 127, o0 = (tid >> 7) * 2;
    ull tw2[16];
    #pragma unroll
    for (int m2 = 0; m2 < 16; m2++) {
        int idx = (m2*w) & 127;
        tw2[m2] = pk2(ct[idx], -st[idx]);
    }
    float s00 = sk[o0*4+0], s01 = sk[o0*4+1], s02 = sk[o0*4+2], s03 = sk[o0*4+3];
    float s10 = sk[o0*4+4], s11 = sk[o0*4+5], s12 = sk[o0*4+6], s13 = sk[o0*4+7];
    size_t outbase = ((size_t)(s*512 + n)*4 + o0) * HW;
    size_t xbase   = (size_t)n * 4 * HW;

    for (int h = 0; h < 128; h++) {
        const ull* U0 = (const ull*)(U + (o0 << 11) + (h << 4));
        const ull* U1 = (const ull*)(U + ((o0+1) << 11) + (h << 4));
        ull a0 = 0, a1 = 0;
        #pragma unroll
        for (int m2 = 0; m2 < 16; m2++) {
            FMA2(a0, U0[m2], tw2[m2]);
            FMA2(a1, U1[m2], tw2[m2]);
        }
        float2 r0 = upk(a0), r1 = upk(a1);
        float v0 = r0.x + r0.y, v1 = r1.x + r1.y;
        int p = (h << 7) + w;
        float x0 = x[xbase + p],        x1 = x[xbase + HW + p];
        float x2 = x[xbase + 2*HW + p], x3 = x[xbase + 3*HW + p];
        v0 += s00*x0 + s01*x1 + s02*x2 + s03*x3;
        v1 += s10*x0 + s11*x1 + s12*x2 + s13*x3;
        g_kqv[outbase + p]      = v0;
        g_kqv[outbase + HW + p] = v1;
    }
}

// ---------------- attention --------------------------------------------------
__global__ void k_zero() {
    g_S[blockIdx.x*256 + threadIdx.x] = 0.f;
}

// ch chunk = 128 -> smem 66560 B -> 3 blocks/SM (24 warps: latency hiding)
static const int SM_SCORES = 2*64*130*4;   // 66560 B

__global__ void k_scores() {
    extern __shared__ float sm[];
    float* qs = sm;             // [64][130]  (row stride 130 f = 65 ull, odd)
    float* ks = sm + 64*130;
    const int b = blockIdx.y, ch = blockIdx.x, tid = threadIdx.x;
    size_t qoff = ((size_t)512 + (size_t)b*64) * 65536 + (size_t)ch*128;  // q = kqv[1]
    size_t koff = ((size_t)b*64) * 65536 + (size_t)ch*128;                // k = kqv[0]
    for (int i = tid; i < 8192; i += 256) {
        int t = i >> 7, j = i & 127;
        qs[t*130 + j] = g_kqv[qoff + (size_t)t*65536 + j];
        ks[t*130 + j] = g_kqv[koff + (size_t)t*65536 + j];
    }
    __syncthreads();
    int t = tid >> 2, sl = tid & 3;
    ull acc[16];
    #pragma unroll
    for (int j = 0; j < 16; j++) acc[j] = 0;
    const ull* qrow = (const ull*)(qs + t*130);
    for (int kk = 0; kk < 64; kk++) {
        ull q2 = qrow[kk];
        #pragma unroll
        for (int j = 0; j < 16; j++) {
            ull k2 = *(const ull*)(ks + (sl + 4*j)*130 + 2*kk);
            FMA2(acc[j], q2, k2);
        }
    }
    #pragma unroll
    for (int j = 0; j < 16; j++) {
        float2 r = upk(acc[j]);
        atomicAdd(&g_S[(b*64 + t)*64 + sl + 4*j], (r.x + r.y) * (1.f/65536.f));
    }
}

__global__ void k_softmax() {
    int b = blockIdx.x, t = threadIdx.x;           // 8 x 64
    float* row = &g_S[(b*64 + t)*64];
    float mx = -1e30f;
    for (int s = 0; s < 64; s++) mx = fmaxf(mx, row[s]);
    float sum = 0.f;
    for (int s = 0; s < 64; s++) { float v = expf(row[s] - mx); row[s] = v; sum += v; }
    float inv = 1.f / sum;
    for (int s = 0; s < 64; s++) row[s] *= inv;
}

// 2 px per thread, 32 t per z-half; attn weights duplicate-packed in smem
__global__ void k_attnv() {
    __shared__ ull As2[2048];                      // [32 t][64 s] pk(a,a)
    const int b = blockIdx.y, z = blockIdx.z, tid = threadIdx.x;
    const int p = blockIdx.x * 512 + tid * 2;
    for (int i = tid; i < 2048; i += 256) {
        float a = g_S[b*4096 + z*2048 + i];
        As2[i] = pk2(a, a);
    }
    __syncthreads();
    ull acc[32];
    #pragma unroll
    for (int t = 0; t < 32; t++) acc[t] = 0;
    size_t vbase = ((size_t)1024 + (size_t)b*64) * 65536 + p;   // v = kqv[2]
    for (int s = 0; s < 64; s++) {
        ull vv = *(const ull*)(g_kqv + vbase + (size_t)s*65536);
        #pragma unroll
        for (int t = 0; t < 32; t++) FMA2(acc[t], vv, As2[t*64 + s]);
    }
    size_t obase = (size_t)b * 4194304 + (size_t)z * 32 * 65536 + p;
    #pragma unroll
    for (int t = 0; t < 32; t++) {
        float2 r = upk(acc[t]);
        *(float2*)(g_att + obase + (size_t)t*65536) = r;
    }
}

// ---------------- InstanceNorm2d + exact GELU (in place) --------------------
__global__ void k_inorm() {
    __shared__ float w1s[8], w2s[8];
    float* ptr = g_att + (size_t)blockIdx.x * HW;
    const int tid = threadIdx.x;
    float s1 = 0.f, s2 = 0.f;
    for (int i = tid; i < HW; i += 256) { float v = ptr[i]; s1 += v; s2 += v*v; }
    for (int off = 16; off; off >>= 1) {
        s1 += __shfl_down_sync(0xffffffffu, s1, off);
        s2 += __shfl_down_sync(0xffffffffu, s2, off);
    }
    if ((tid & 31) == 0) { w1s[tid >> 5] = s1; w2s[tid >> 5] = s2; }
    __syncthreads();
    if (tid == 0) {
        float a = 0.f, c = 0.f;
        for (int i = 0; i < 8; i++) { a += w1s[i]; c += w2s[i]; }
        w1s[0] = a * (1.f/HW); w2s[0] = c * (1.f/HW);
    }
    __syncthreads();
    float mu = w1s[0];
    float inv = rsqrtf(w2s[0] - mu*mu + 1e-5f);
    for (int i = tid; i < HW; i += 256) {
        float v = (ptr[i] - mu) * inv;
        ptr[i] = v * normcdff(v);
    }
}

// ---------------- end spectral multiply (FMA2 split-accumulator) ------------
__global__ void k_spec_end(const float* __restrict__ w1r, const float* __restrict__ w1i,
                           const float* __restrict__ w2r, const float* __restrict__ w2i) {
    const int m = threadIdx.x;                 // 512
    const int o0 = blockIdx.x * 2;             // 128 blocks
    bool top = m < 256;
    int mm = top ? m : (m - 256);
    const float* wr = top ? w1r : w2r;
    const float* wi = top ? w1i : w2i;
    ull r0[8], i0[8], r1[8], i1[8];
    #pragma unroll
    for (int b = 0; b < 8; b++) { r0[b]=0; i0[b]=0; r1[b]=0; i1[b]=0; }
    const ull* XF = (const ull*)g_XF + m;
    for (int i = 0; i < 256; i++) {
        float wr0 = wr[((size_t)i*256 + o0    )*256 + mm];
        float wi0 = wi[((size_t)i*256 + o0    )*256 + mm];
        float wr1 = wr[((size_t)i*256 + o0 + 1)*256 + mm];
        float wi1 = wi[((size_t)i*256 + o0 + 1)*256 + mm];
        ull wr02 = pk2(wr0, wr0), wi02 = pk2(wi0, wi0);
        ull wr12 = pk2(wr1, wr1), wi12 = pk2(wi1, wi1);
        #pragma unroll
        for (int b = 0; b < 8; b++) {
            ull X = XF[(size_t)(b*256 + i) * NMODE];
            FMA2(r0[b], X, wr02);  FMA2(i0[b], X, wi02);
            FMA2(r1[b], X, wr12);  FMA2(i1[b], X, wi12);
        }
    }
    #pragma unroll
    for (int b = 0; b < 8; b++) {
        float2 ar = upk(r0[b]), ai = upk(i0[b]);
        g_EOF[((size_t)(b*256 + o0    )) * NMODE + m] = make_float2(ar.x - ai.y, ai.x + ar.y);
        float2 br = upk(r1[b]), bi = upk(i1[b]);
        g_EOF[((size_t)(b*256 + o0 + 1)) * NMODE + m] = make_float2(br.x - bi.y, bi.x + br.y);
    }
}

// ---------------- end inverse partial DFT -> d_out --------------------------
__global__ void k_idft_end(float* __restrict__ out) {
    __shared__ float2 OFs[512];
    __shared__ float2 U[2048];
    __shared__ ull cc2[128], ss2[128];
    __shared__ float ct[128], st[128];
    const int tid = threadIdx.x;               // 256
    const int plane = blockIdx.x;              // 2048
    if (tid < 128) {
        float a = (float)tid * (PI2/128.f);
        float c = cosf(a), sn = sinf(a);
        ct[tid] = c; st[tid] = sn;
        cc2[tid] = pk2(c, c); ss2[tid] = pk2(sn, sn);
    }
    for (int i = tid; i < 512; i += 256) OFs[i] = g_EOF[(size_t)plane*512 + i];
    __syncthreads();

    {   // phase 1 (register-tiled FMA2)
        const int h  = tid >> 1;
        const int jh = (tid & 1) * 8;
        ull ar[8], ai[8];
        #pragma unroll
        for (int j = 0; j < 8; j++) { ar[j] = 0; ai[j] = 0; }
        const ull* Xb = (const ull*)OFs + jh;
        #pragma unroll 8
        for (int m1i = 0; m1i < 32; m1i++) {
            int r = (m1i < 16) ? m1i : (m1i + 96);
            int idx = (r * h) & 127;
            ull cc = cc2[idx], ss = ss2[idx];
            #pragma unroll
            for (int j = 0; j < 8; j++) {
                ull X = Xb[m1i*16 + j];
                FMA2(ar[j], X, cc);
                FMA2(ai[j], X, ss);
            }
        }
        #pragma unroll
        for (int j = 0; j < 8; j++) {
            float2 r2 = upk(ar[j]), i2 = upk(ai[j]);
            float ux = r2.x - i2.y;
            float uy = i2.x + r2.y;
            float a = ((jh + j) == 0) ? 1.f : 2.f;
            U[(h << 4) + jh + j] = make_float2(ux*a, uy*a);
        }
    }
    __syncthreads();

    int w = tid & 127, h0 = (tid >> 7) * 64;
    ull tw2[16];
    #pragma unroll
    for (int m2 = 0; m2 < 16; m2++) {
        int idx = (m2*w) & 127;
        tw2[m2] = pk2(ct[idx], -st[idx]);
    }
    for (int h = h0; h < h0 + 64; h++) {
        const ull* Up = (const ull*)(U + (h << 4));
        ull a2 = 0;
        #pragma unroll
        for (int m2 = 0; m2 < 16; m2++) FMA2(a2, Up[m2], tw2[m2]);
        float2 r = upk(a2);
        out[(size_t)plane*HW + (h << 7) + w] = r.x + r.y;
    }
}

// ---------------- end pointwise skip GEMM (accumulates into d_out) ----------
static const int SM_ENDSK = 32*128*8 + 32*128*4;   // 49152 B

__global__ void k_endskip(const float* __restrict__ skip, float* __restrict__ out) {
    extern __shared__ __align__(16) unsigned char smraw[];
    ull*   Ssp = (ull*)smraw;                  // [32 k][128 o] pk(s,s)
    float* Gs  = (float*)(Ssp + 4096);         // [32 k][128 p]
    const int b = blockIdx.z, o0 = blockIdx.y * 128, p0 = blockIdx.x * 128;
    const int tid = threadIdx.x;
    const int oy = tid >> 4, px = tid & 15;
    ull acc[8][4];
    #pragma unroll
    for (int j = 0; j < 8; j++)
        #pragma unroll
        for (int jj = 0; jj < 4; jj++) acc[j][jj] = 0;

    for (int kc = 0; kc < 256; kc += 32) {
        for (int i = tid; i < 4096; i += 256) {
            int o = i & 127, k = i >> 7;
            float s = skip[(size_t)(o0 + o)*256 + kc + k];
            Ssp[k*128 + o] = pk2(s, s);
        }
        for (int i = tid; i < 4096; i += 256) {
            int c = i & 127, ir = i >> 7;
            Gs[ir*128 + c] = g_att[((size_t)b*256 + kc + ir) * HW + p0 + c];
        }
        __syncthreads();
        #pragma unroll 4
        for (int k = 0; k < 32; k++) {
            ull gv[4];
            const ull* gp = (const ull*)(Gs + k*128);
            #pragma unroll
            for (int jj = 0; jj < 4; jj++) gv[jj] = gp[px + 16*jj];
            #pragma unroll
            for (int j = 0; j < 8; j++) {
                ull sv = Ssp[k*128 + oy + 16*j];
                #pragma unroll
                for (int jj = 0; jj < 4; jj++) FMA2(acc[j][jj], gv[jj], sv);
            }
        }
        __syncthreads();
    }
    #pragma unroll
    for (int j = 0; j < 8; j++)
        #pragma unroll
        for (int jj = 0; jj < 4; jj++) {
            size_t oidx = ((size_t)b*256 + o0 + oy + 16*j) * HW + p0 + 2*px + 32*jj;
            float2 r = upk(acc[j][jj]);
            float2* op = (float2*)(out + oidx);
            float2 cur = *op;
            cur.x += r.x; cur.y += r.y;
            *op = cur;
        }
}

// ---------------- launch -----------------------------------------------------
extern "C" void kernel_launch(void* const* d_in, const int* in_sizes, int n_in,
                              void* d_out, int out_size) {
    const float* x        = (const float*)d_in[0];
    const float* kqv_w1r  = (const float*)d_in[1];
    const float* kqv_w1i  = (const float*)d_in[2];
    const float* kqv_w2r  = (const float*)d_in[3];
    const float* kqv_w2i  = (const float*)d_in[4];
    const float* kqv_skip = (const float*)d_in[5];
    const float* end_w1r  = (const float*)d_in[6];
    const float* end_w1i  = (const float*)d_in[7];
    const float* end_w2r  = (const float*)d_in[8];
    const float* end_w2i  = (const float*)d_in[9];
    const float* end_skip = (const float*)d_in[10];
    float* out = (float*)d_out;

    cudaFuncSetAttribute(k_fwd_dft,  cudaFuncAttributeMaxDynamicSharedMemorySize, SM_FWD);
    cudaFuncSetAttribute(k_idft_kqv, cudaFuncAttributeMaxDynamicSharedMemorySize, SM_IDFTK);
    cudaFuncSetAttribute(k_scores,   cudaFuncAttributeMaxDynamicSharedMemorySize, SM_SCORES);
    cudaFuncSetAttribute(k_endskip,  cudaFuncAttributeMaxDynamicSharedMemorySize, SM_ENDSK);

    float2* gXF;  cudaGetSymbolAddress((void**)&gXF,  g_XF);
    float*  gAtt; cudaGetSymbolAddress((void**)&gAtt, g_att);

    // launch order: slot #4 gets profiled by ncu -> k_idft_kqv
    k_zero<<<128, 256>>>();                                         // 1
    k_fwd_dft<<<2048, 256, SM_FWD>>>(x, gXF);                       // 2
    k_spec_kqv<<<1536, 512>>>(kqv_w1r, kqv_w1i, kqv_w2r, kqv_w2i);  // 3
    k_idft_kqv<<<1536, 256, SM_IDFTK>>>(x, kqv_skip);               // 4 <- profiled

    // attention over tokens
    k_scores<<<dim3(512, 8), 256, SM_SCORES>>>();
    k_softmax<<<8, 64>>>();
    k_attnv<<<dim3(128, 8, 2), 256>>>();

    // instance norm + gelu
    k_inorm<<<2048, 256>>>();

    // stage 2: end FNO block
    k_fwd_dft<<<2048, 256, SM_FWD>>>(gAtt, gXF);
    k_spec_end<<<128, 512>>>(end_w1r, end_w1i, end_w2r, end_w2i);
    k_idft_end<<<2048, 256>>>(out);
    k_endskip<<<dim3(128, 2, 8), 256, SM_ENDSK>>>(end_skip, out);
}

// round 14
// speedup vs baseline: 1.4862x; 1.0632x over previous
#include <cuda_runtime.h>
#include <math.h>

#define HW    16384
#define NMODE 512
#define PI2   6.28318530717958647692f

typedef unsigned long long ull;

// packed fp32x2 helpers (sm_100+: FFMA2)
__device__ __forceinline__ ull pk2(float a, float b) {
    ull r; asm("mov.b64 %0, {%1,%2};" : "=l"(r) : "f"(a), "f"(b)); return r;
}
__device__ __forceinline__ float2 upk(ull v) {
    float2 r; asm("mov.b64 {%0,%1}, %2;" : "=f"(r.x), "=f"(r.y) : "l"(v)); return r;
}
#define FMA2(d, a, b) asm("fma.rn.f32x2 %0, %1, %2, %0;" : "+l"(d) : "l"(a), "l"(b))

// ---- scratch (device globals; 16B-aligned for 8B vector accesses) ----
__device__ __align__(16) float2 g_XF [2048 * NMODE];
__device__ __align__(16) float2 g_OF [3 * 2048 * NMODE];
__device__ __align__(16) float  g_kqv[100663296];     // [3][512][4][16384]
__device__ __align__(16) float  g_S  [32768];         // [8][64][64]
__device__ __align__(16) float  g_att[33554432];      // [8][256][16384]
__device__ __align__(16) float2 g_EOF[2048 * NMODE];

// ---------------- forward partial DFT: 128x128 plane -> 32x16 modes ----------
// layout (bytes): tw2[2048]u @0 | cc2[128]u @16384 | ss2[128]u @17408 |
//                 xs[128*129]f @18432 | T1[128*16]f2 @84480 | ct,st @100864
static const int SM_FWD = 101888;

__global__ void k_fwd_dft(const float* __restrict__ src, float2* __restrict__ dst) {
    extern __shared__ __align__(16) unsigned char smraw[];
    ull*    tw2 = (ull*)smraw;                       // [16][128] (c, -s)
    ull*    cc2 = tw2 + 2048;                        // (c,c)
    ull*    ss2 = cc2 + 128;                         // (s,s)
    float*  xs  = (float*)(smraw + 18432);           // [128][129]
    float2* T1  = (float2*)(smraw + 84480);          // [128][16]
    float*  ct  = (float*)(smraw + 100864);
    float*  st  = ct + 128;
    const int tid = threadIdx.x;                     // 256
    const float* x = src + (size_t)blockIdx.x * HW;

    if (tid < 128) {
        float a = (float)tid * (PI2/128.f);
        float c = cosf(a), s = sinf(a);
        ct[tid] = c; st[tid] = s;
        cc2[tid] = pk2(c, c); ss2[tid] = pk2(s, s);
    }
    for (int i = tid; i < HW; i += 256) xs[(i >> 7)*129 + (i & 127)] = x[i];
    __syncthreads();

    for (int i = tid; i < 2048; i += 256) {
        int idx = ((i >> 7) * (i & 127)) & 127;
        tw2[i] = pk2(ct[idx], -st[idx]);
    }
    __syncthreads();

    {   // phase 1 (radix-2 fold over w): T1[h][m2] = sum_{w<64} (x[w] +- x[w+64]) tw[m2][w]
        // tw[m2][w+64] = (-1)^m2 tw[m2][w]; even m2 -> xp, odd m2 -> xm
        int h = tid >> 1, m2b = (tid & 1) * 8;       // m2 = m2b + j, parity = j&1
        ull acc[8];
        #pragma unroll
        for (int j = 0; j < 8; j++) acc[j] = 0;
        const float* xr = xs + h*129;
        for (int w = 0; w < 64; w++) {
            float xa = xr[w], xb = xr[w + 64];
            float xp = xa + xb, xm = xa - xb;
            ull xp2 = pk2(xp, xp), xm2 = pk2(xm, xm);
            #pragma unroll
            for (int j = 0; j < 8; j++)
                FMA2(acc[j], (j & 1) ? xm2 : xp2, tw2[(m2b + j)*128 + w]);
        }
        #pragma unroll
        for (int j = 0; j < 8; j++) *(ull*)&T1[h*16 + m2b + j] = acc[j];
    }
    __syncthreads();

    // phase 2 (FMA2 split-accumulator): fold h with row-mode twiddles
    #pragma unroll
    for (int rep = 0; rep < 2; rep++) {
        int om  = tid + rep*256;
        int m1i = om >> 4, m2 = om & 15;
        int r   = (m1i < 16) ? m1i : (m1i + 96);
        ull ar = 0, ai = 0;
        const ull* T1u = (const ull*)T1 + m2;
        #pragma unroll 4
        for (int h = 0; h < 128; h++) {
            int idx = (r * h) & 127;
            ull t = T1u[h*16];
            FMA2(ar, t, cc2[idx]);     // (tx c, ty c)
            FMA2(ai, t, ss2[idx]);     // (tx s, ty s)
        }
        float2 a = upk(ar), b = upk(ai);
        dst[(size_t)blockIdx.x * NMODE + om] =
            make_float2((a.x + b.y)*(1.f/16384.f), (a.y - b.x)*(1.f/16384.f));
    }
}

// ---------------- kqv spectral multiply ----------------
__global__ void k_spec_kqv(const float* __restrict__ w1r, const float* __restrict__ w1i,
                           const float* __restrict__ w2r, const float* __restrict__ w2i) {
    int s = blockIdx.x >> 9, n = blockIdx.x & 511;
    int m = threadIdx.x;                 // 512
    bool top = m < 256;
    int mm = top ? m : (m - 256);
    const float* wr = top ? w1r : w2r;
    const float* wi = top ? w1i : w2i;

    float2 xv[4];
    #pragma unroll
    for (int i = 0; i < 4; i++) xv[i] = g_XF[(size_t)(n*4 + i) * NMODE + m];

    #pragma unroll
    for (int o = 0; o < 4; o++) {
        float ax = 0.f, ay = 0.f;
        #pragma unroll
        for (int i = 0; i < 4; i++) {
            float a = wr[s*4096 + (i*4 + o)*256 + mm];
            float b = wi[s*4096 + (i*4 + o)*256 + mm];
            ax += xv[i].x*a - xv[i].y*b;
            ay += xv[i].x*b + xv[i].y*a;
        }
        g_OF[((size_t)(s*512 + n)*4 + o) * NMODE + m] = make_float2(ax, ay);
    }
}

// ---------------- kqv inverse partial DFT + pointwise skip -------------------
static const int SM_IDFTK = 2048*8 + 8192*8 + 128*8*2 + 256*4 + 16*4;   // 85056 B

__global__ void __launch_bounds__(512, 2)
k_idft_kqv(const float* __restrict__ x, const float* __restrict__ skip) {
    extern __shared__ float sm[];
    float2* OFs = (float2*)sm;                 // [4][32][16]
    float2* U   = OFs + 2048;                  // [4][128][16]
    ull*    cc2 = (ull*)(U + 8192);            // (c,c)
    ull*    ss2 = cc2 + 128;                   // (s,s)
    float*  ct  = (float*)(ss2 + 128);
    float*  st  = ct + 128;
    float*  sk  = st + 128;                    // [4][4] (o,i)
    const int tid = threadIdx.x;               // 512
    const int s = blockIdx.x >> 9, n = blockIdx.x & 511;

    if (tid < 128) {
        float a = (float)tid * (PI2/128.f);
        float c = cosf(a), sn = sinf(a);
        ct[tid] = c; st[tid] = sn;
        cc2[tid] = pk2(c, c); ss2[tid] = pk2(sn, sn);
    }
    if (tid < 16)  sk[tid] = skip[s*16 + tid];
    for (int i = tid; i < 2048; i += 512)
        OFs[i] = g_OF[((size_t)(s*512 + n)*4) * NMODE + i];
    __syncthreads();

    // phase 1 (register-tiled, FMA2): 1024 units (o,h,jh), 2 per thread
    #pragma unroll
    for (int it = 0; it < 2; it++) {
        const int u  = tid + it*512;
        const int o  = u >> 8;
        const int h  = (u >> 1) & 127;
        const int jh = (u & 1) * 8;
        ull ar[8], ai[8];
        #pragma unroll
        for (int j = 0; j < 8; j++) { ar[j] = 0; ai[j] = 0; }
        const ull* Xb = (const ull*)OFs + o*512 + jh;
        #pragma unroll 8
        for (int m1i = 0; m1i < 32; m1i++) {
            int r = (m1i < 16) ? m1i : (m1i + 96);
            int idx = (r * h) & 127;
            ull cc = cc2[idx], ss = ss2[idx];
            #pragma unroll
            for (int j = 0; j < 8; j++) {
                ull X = Xb[m1i*16 + j];
                FMA2(ar[j], X, cc);
                FMA2(ai[j], X, ss);
            }
        }
        #pragma unroll
        for (int j = 0; j < 8; j++) {
            float2 r2 = upk(ar[j]), i2 = upk(ai[j]);
            float ux = r2.x - i2.y;
            float uy = i2.x + r2.y;
            float a = ((jh + j) == 0) ? 1.f : 2.f;
            U[(o << 11) + (h << 4) + jh + j] = make_float2(ux*a, uy*a);
        }
    }
    __syncthreads();

    // phase 2 (radix-2 fold over w): even/odd m2 accumulators give w and w+64
    // from ONE U-row read.  thread = (wp 64, o 4, hh 2)
    const int wp = tid & 63, o = (tid >> 6) & 3, hh = tid >> 8;
    ull tw2[16];
    #pragma unroll
    for (int m2 = 0; m2 < 16; m2++) {
        int idx = (m2*wp) & 127;
        tw2[m2] = pk2(ct[idx], -st[idx]);
    }
    const float sk0 = sk[o*4+0], sk1 = sk[o*4+1], sk2 = sk[o*4+2], sk3 = sk[o*4+3];
    const size_t outbase = ((size_t)(s*512 + n)*4 + o) * HW;
    const size_t xbase   = (size_t)n * 4 * HW;

    for (int h = hh*64; h < hh*64 + 64; h++) {
        const ull* Ur = (const ull*)(U + (o << 11) + (h << 4));
        ull ae = 0, ao = 0;
        #pragma unroll
        for (int m2 = 0; m2 < 16; m2 += 2) {
            FMA2(ae, Ur[m2],     tw2[m2]);
            FMA2(ao, Ur[m2 + 1], tw2[m2 + 1]);
        }
        float2 re = upk(ae), ro = upk(ao);
        float ve = re.x + re.y, vo = ro.x + ro.y;
        float va = ve + vo;                    // w = wp
        float vb = ve - vo;                    // w = wp + 64
        int p = (h << 7) + wp;
        float x0 = x[xbase + p],           x1 = x[xbase + HW + p];
        float x2 = x[xbase + 2*HW + p],    x3 = x[xbase + 3*HW + p];
        float y0 = x[xbase + p + 64],      y1 = x[xbase + HW + p + 64];
        float y2 = x[xbase + 2*HW + p+64], y3 = x[xbase + 3*HW + p + 64];
        va += sk0*x0 + sk1*x1 + sk2*x2 + sk3*x3;
        vb += sk0*y0 + sk1*y1 + sk2*y2 + sk3*y3;
        g_kqv[outbase + p]      = va;
        g_kqv[outbase + p + 64] = vb;
    }
}

// ---------------- attention --------------------------------------------------
__global__ void k_zero() {
    g_S[blockIdx.x*256 + threadIdx.x] = 0.f;
}

// ch chunk = 128 -> smem 66560 B -> 3 blocks/SM (24 warps: latency hiding)
static const int SM_SCORES = 2*64*130*4;   // 66560 B

__global__ void k_scores() {
    extern __shared__ float sm[];
    float* qs = sm;             // [64][130]  (row stride 130 f = 65 ull, odd)
    float* ks = sm + 64*130;
    const int b = blockIdx.y, ch = blockIdx.x, tid = threadIdx.x;
    size_t qoff = ((size_t)512 + (size_t)b*64) * 65536 + (size_t)ch*128;  // q = kqv[1]
    size_t koff = ((size_t)b*64) * 65536 + (size_t)ch*128;                // k = kqv[0]
    for (int i = tid; i < 8192; i += 256) {
        int t = i >> 7, j = i & 127;
        qs[t*130 + j] = g_kqv[qoff + (size_t)t*65536 + j];
        ks[t*130 + j] = g_kqv[koff + (size_t)t*65536 + j];
    }
    __syncthreads();
    int t = tid >> 2, sl = tid & 3;
    ull acc[16];
    #pragma unroll
    for (int j = 0; j < 16; j++) acc[j] = 0;
    const ull* qrow = (const ull*)(qs + t*130);
    for (int kk = 0; kk < 64; kk++) {
        ull q2 = qrow[kk];
        #pragma unroll
        for (int j = 0; j < 16; j++) {
            ull k2 = *(const ull*)(ks + (sl + 4*j)*130 + 2*kk);
            FMA2(acc[j], q2, k2);
        }
    }
    #pragma unroll
    for (int j = 0; j < 16; j++) {
        float2 r = upk(acc[j]);
        atomicAdd(&g_S[(b*64 + t)*64 + sl + 4*j], (r.x + r.y) * (1.f/65536.f));
    }
}

__global__ void k_softmax() {
    int b = blockIdx.x, t = threadIdx.x;           // 8 x 64
    float* row = &g_S[(b*64 + t)*64];
    float mx = -1e30f;
    for (int s = 0; s < 64; s++) mx = fmaxf(mx, row[s]);
    float sum = 0.f;
    for (int s = 0; s < 64; s++) { float v = expf(row[s] - mx); row[s] = v; sum += v; }
    float inv = 1.f / sum;
    for (int s = 0; s < 64; s++) row[s] *= inv;
}

// 2 px per thread, 32 t per z-half; attn weights duplicate-packed in smem
__global__ void k_attnv() {
    __shared__ ull As2[2048];                      // [32 t][64 s] pk(a,a)
    const int b = blockIdx.y, z = blockIdx.z, tid = threadIdx.x;
    const int p = blockIdx.x * 512 + tid * 2;
    for (int i = tid; i < 2048; i += 256) {
        float a = g_S[b*4096 + z*2048 + i];
        As2[i] = pk2(a, a);
    }
    __syncthreads();
    ull acc[32];
    #pragma unroll
    for (int t = 0; t < 32; t++) acc[t] = 0;
    size_t vbase = ((size_t)1024 + (size_t)b*64) * 65536 + p;   // v = kqv[2]
    for (int s = 0; s < 64; s++) {
        ull vv = *(const ull*)(g_kqv + vbase + (size_t)s*65536);
        #pragma unroll
        for (int t = 0; t < 32; t++) FMA2(acc[t], vv, As2[t*64 + s]);
    }
    size_t obase = (size_t)b * 4194304 + (size_t)z * 32 * 65536 + p;
    #pragma unroll
    for (int t = 0; t < 32; t++) {
        float2 r = upk(acc[t]);
        *(float2*)(g_att + obase + (size_t)t*65536) = r;
    }
}

// ---------------- InstanceNorm2d + exact GELU (in place) --------------------
__global__ void k_inorm() {
    __shared__ float w1s[8], w2s[8];
    float* ptr = g_att + (size_t)blockIdx.x * HW;
    const int tid = threadIdx.x;
    float s1 = 0.f, s2 = 0.f;
    for (int i = tid; i < HW; i += 256) { float v = ptr[i]; s1 += v; s2 += v*v; }
    for (int off = 16; off; off >>= 1) {
        s1 += __shfl_down_sync(0xffffffffu, s1, off);
        s2 += __shfl_down_sync(0xffffffffu, s2, off);
    }
    if ((tid & 31) == 0) { w1s[tid >> 5] = s1; w2s[tid >> 5] = s2; }
    __syncthreads();
    if (tid == 0) {
        float a = 0.f, c = 0.f;
        for (int i = 0; i < 8; i++) { a += w1s[i]; c += w2s[i]; }
        w1s[0] = a * (1.f/HW); w2s[0] = c * (1.f/HW);
    }
    __syncthreads();
    float mu = w1s[0];
    float inv = rsqrtf(w2s[0] - mu*mu + 1e-5f);
    for (int i = tid; i < HW; i += 256) {
        float v = (ptr[i] - mu) * inv;
        ptr[i] = v * normcdff(v);
    }
}

// ---------------- end spectral multiply (FMA2 split-accumulator) ------------
__global__ void k_spec_end(const float* __restrict__ w1r, const float* __restrict__ w1i,
                           const float* __restrict__ w2r, const float* __restrict__ w2i) {
    const int m = threadIdx.x;                 // 512
    const int o0 = blockIdx.x * 2;             // 128 blocks
    bool top = m < 256;
    int mm = top ? m : (m - 256);
    const float* wr = top ? w1r : w2r;
    const float* wi = top ? w1i : w2i;
    ull r0[8], i0[8], r1[8], i1[8];
    #pragma unroll
    for (int b = 0; b < 8; b++) { r0[b]=0; i0[b]=0; r1[b]=0; i1[b]=0; }
    const ull* XF = (const ull*)g_XF + m;
    for (int i = 0; i < 256; i++) {
        float wr0 = wr[((size_t)i*256 + o0    )*256 + mm];
        float wi0 = wi[((size_t)i*256 + o0    )*256 + mm];
        float wr1 = wr[((size_t)i*256 + o0 + 1)*256 + mm];
        float wi1 = wi[((size_t)i*256 + o0 + 1)*256 + mm];
        ull wr02 = pk2(wr0, wr0), wi02 = pk2(wi0, wi0);
        ull wr12 = pk2(wr1, wr1), wi12 = pk2(wi1, wi1);
        #pragma unroll
        for (int b = 0; b < 8; b++) {
            ull X = XF[(size_t)(b*256 + i) * NMODE];
            FMA2(r0[b], X, wr02);  FMA2(i0[b], X, wi02);
            FMA2(r1[b], X, wr12);  FMA2(i1[b], X, wi12);
        }
    }
    #pragma unroll
    for (int b = 0; b < 8; b++) {
        float2 ar = upk(r0[b]), ai = upk(i0[b]);
        g_EOF[((size_t)(b*256 + o0    )) * NMODE + m] = make_float2(ar.x - ai.y, ai.x + ar.y);
        float2 br = upk(r1[b]), bi = upk(i1[b]);
        g_EOF[((size_t)(b*256 + o0 + 1)) * NMODE + m] = make_float2(br.x - bi.y, bi.x + br.y);
    }
}

// ---------------- end inverse partial DFT -> d_out --------------------------
__global__ void k_idft_end(float* __restrict__ out) {
    __shared__ float2 OFs[512];
    __shared__ float2 U[2048];
    __shared__ ull cc2[128], ss2[128];
    __shared__ float ct[128], st[128];
    const int tid = threadIdx.x;               // 256
    const int plane = blockIdx.x;              // 2048
    if (tid < 128) {
        float a = (float)tid * (PI2/128.f);
        float c = cosf(a), sn = sinf(a);
        ct[tid] = c; st[tid] = sn;
        cc2[tid] = pk2(c, c); ss2[tid] = pk2(sn, sn);
    }
    for (int i = tid; i < 512; i += 256) OFs[i] = g_EOF[(size_t)plane*512 + i];
    __syncthreads();

    {   // phase 1 (register-tiled FMA2)
        const int h  = tid >> 1;
        const int jh = (tid & 1) * 8;
        ull ar[8], ai[8];
        #pragma unroll
        for (int j = 0; j < 8; j++) { ar[j] = 0; ai[j] = 0; }
        const ull* Xb = (const ull*)OFs + jh;
        #pragma unroll 8
        for (int m1i = 0; m1i < 32; m1i++) {
            int r = (m1i < 16) ? m1i : (m1i + 96);
            int idx = (r * h) & 127;
            ull cc = cc2[idx], ss = ss2[idx];
            #pragma unroll
            for (int j = 0; j < 8; j++) {
                ull X = Xb[m1i*16 + j];
                FMA2(ar[j], X, cc);
                FMA2(ai[j], X, ss);
            }
        }
        #pragma unroll
        for (int j = 0; j < 8; j++) {
            float2 r2 = upk(ar[j]), i2 = upk(ai[j]);
            float ux = r2.x - i2.y;
            float uy = i2.x + r2.y;
            float a = ((jh + j) == 0) ? 1.f : 2.f;
            U[(h << 4) + jh + j] = make_float2(ux*a, uy*a);
        }
    }
    __syncthreads();

    // phase 2 (radix-2 fold over w): thread = (wp 64, hq 4), 32 h each
    const int wp = tid & 63, hq = tid >> 6;
    ull tw2[16];
    #pragma unroll
    for (int m2 = 0; m2 < 16; m2++) {
        int idx = (m2*wp) & 127;
        tw2[m2] = pk2(ct[idx], -st[idx]);
    }
    for (int h = hq*32; h < hq*32 + 32; h++) {
        const ull* Ur = (const ull*)(U + (h << 4));
        ull ae = 0, ao = 0;
        #pragma unroll
        for (int m2 = 0; m2 < 16; m2 += 2) {
            FMA2(ae, Ur[m2],     tw2[m2]);
            FMA2(ao, Ur[m2 + 1], tw2[m2 + 1]);
        }
        float2 re = upk(ae), ro = upk(ao);
        float ve = re.x + re.y, vo = ro.x + ro.y;
        size_t base = (size_t)plane*HW + (h << 7) + wp;
        out[base]      = ve + vo;
        out[base + 64] = ve - vo;
    }
}

// ---------------- end pointwise skip GEMM (accumulates into d_out) ----------
static const int SM_ENDSK = 32*128*8 + 32*128*4;   // 49152 B

__global__ void k_endskip(const float* __restrict__ skip, float* __restrict__ out) {
    extern __shared__ __align__(16) unsigned char smraw[];
    ull*   Ssp = (ull*)smraw;                  // [32 k][128 o] pk(s,s)
    float* Gs  = (float*)(Ssp + 4096);         // [32 k][128 p]
    const int b = blockIdx.z, o0 = blockIdx.y * 128, p0 = blockIdx.x * 128;
    const int tid = threadIdx.x;
    const int oy = tid >> 4, px = tid & 15;
    ull acc[8][4];
    #pragma unroll
    for (int j = 0; j < 8; j++)
        #pragma unroll
        for (int jj = 0; jj < 4; jj++) acc[j][jj] = 0;

    for (int kc = 0; kc < 256; kc += 32) {
        for (int i = tid; i < 4096; i += 256) {
            int o = i & 127, k = i >> 7;
            float s = skip[(size_t)(o0 + o)*256 + kc + k];
            Ssp[k*128 + o] = pk2(s, s);
        }
        for (int i = tid; i < 4096; i += 256) {
            int c = i & 127, ir = i >> 7;
            Gs[ir*128 + c] = g_att[((size_t)b*256 + kc + ir) * HW + p0 + c];
        }
        __syncthreads();
        #pragma unroll 4
        for (int k = 0; k < 32; k++) {
            ull gv[4];
            const ull* gp = (const ull*)(Gs + k*128);
            #pragma unroll
            for (int jj = 0; jj < 4; jj++) gv[jj] = gp[px + 16*jj];
            #pragma unroll
            for (int j = 0; j < 8; j++) {
                ull sv = Ssp[k*128 + oy + 16*j];
                #pragma unroll
                for (int jj = 0; jj < 4; jj++) FMA2(acc[j][jj], gv[jj], sv);
            }
        }
        __syncthreads();
    }
    #pragma unroll
    for (int j = 0; j < 8; j++)
        #pragma unroll
        for (int jj = 0; jj < 4; jj++) {
            size_t oidx = ((size_t)b*256 + o0 + oy + 16*j) * HW + p0 + 2*px + 32*jj;
            float2 r = upk(acc[j][jj]);
            float2* op = (float2*)(out + oidx);
            float2 cur = *op;
            cur.x += r.x; cur.y += r.y;
            *op = cur;
        }
}

// ---------------- launch -----------------------------------------------------
extern "C" void kernel_launch(void* const* d_in, const int* in_sizes, int n_in,
                              void* d_out, int out_size) {
    const float* x        = (const float*)d_in[0];
    const float* kqv_w1r  = (const float*)d_in[1];
    const float* kqv_w1i  = (const float*)d_in[2];
    const float* kqv_w2r  = (const float*)d_in[3];
    const float* kqv_w2i  = (const float*)d_in[4];
    const float* kqv_skip = (const float*)d_in[5];
    const float* end_w1r  = (const float*)d_in[6];
    const float* end_w1i  = (const float*)d_in[7];
    const float* end_w2r  = (const float*)d_in[8];
    const float* end_w2i  = (const float*)d_in[9];
    const float* end_skip = (const float*)d_in[10];
    float* out = (float*)d_out;

    cudaFuncSetAttribute(k_fwd_dft,  cudaFuncAttributeMaxDynamicSharedMemorySize, SM_FWD);
    cudaFuncSetAttribute(k_idft_kqv, cudaFuncAttributeMaxDynamicSharedMemorySize, SM_IDFTK);
    cudaFuncSetAttribute(k_scores,   cudaFuncAttributeMaxDynamicSharedMemorySize, SM_SCORES);
    cudaFuncSetAttribute(k_endskip,  cudaFuncAttributeMaxDynamicSharedMemorySize, SM_ENDSK);

    float2* gXF;  cudaGetSymbolAddress((void**)&gXF,  g_XF);
    float*  gAtt; cudaGetSymbolAddress((void**)&gAtt, g_att);

    // launch order: slot #4 gets profiled by ncu -> k_idft_kqv
    k_zero<<<128, 256>>>();                                         // 1
    k_fwd_dft<<<2048, 256, SM_FWD>>>(x, gXF);                       // 2
    k_spec_kqv<<<1536, 512>>>(kqv_w1r, kqv_w1i, kqv_w2r, kqv_w2i);  // 3
    k_idft_kqv<<<1536, 512, SM_IDFTK>>>(x, kqv_skip);               // 4 <- profiled

    // attention over tokens
    k_scores<<<dim3(512, 8), 256, SM_SCORES>>>();
    k_softmax<<<8, 64>>>();
    k_attnv<<<dim3(128, 8, 2), 256>>>();

    // instance norm + gelu
    k_inorm<<<2048, 256>>>();

    // stage 2: end FNO block
    k_fwd_dft<<<2048, 256, SM_FWD>>>(gAtt, gXF);
    k_spec_end<<<128, 512>>>(end_w1r, end_w1i, end_w2r, end_w2i);
    k_idft_end<<<2048, 256>>>(out);
    k_endskip<<<dim3(128, 2, 8), 256, SM_ENDSK>>>(end_skip, out);
}

// round 17
// speedup vs baseline: 1.6025x; 1.0783x over previous
#include <cuda_runtime.h>
#include <math.h>

#define HW    16384
#define NMODE 512
#define PI2   6.28318530717958647692f

typedef unsigned long long ull;

__device__ __forceinline__ ull pk2(float a, float b) {
    ull r; asm("mov.b64 %0, {%1,%2};" : "=l"(r) : "f"(a), "f"(b)); return r;
}
__device__ __forceinline__ float2 upk(ull v) {
    float2 r; asm("mov.b64 {%0,%1}, %2;" : "=f"(r.x), "=f"(r.y) : "l"(v)); return r;
}
#define FMA2(d, a, b) asm("fma.rn.f32x2 %0, %1, %2, %0;" : "+l"(d) : "l"(a), "l"(b))

// ---- scratch ----
__device__ __align__(16) float2 g_XF [2048 * NMODE];
__device__ __align__(16) float2 g_OF [3 * 2048 * NMODE];
__device__ __align__(16) float  g_kqv[100663296];     // [3][512][4][16384]
__device__ __align__(16) float  g_S  [32768];         // [8][64][64]
__device__ __align__(16) float  g_att[33554432];      // [8][256][16384]
__device__ __align__(16) float2 g_EOF[2048 * NMODE];

// ---------------- forward partial DFT: 128x128 plane -> 32x16 modes ----------
// bytes: tw2[2048]u @0 | cc2[128]u | ss2[128]u | xs[128*129]f @18432 |
//        T1[128*16]f2 @84480 | ct,st @100864
static const int SM_FWD = 101888;

__global__ void k_fwd_dft(const float* __restrict__ src, float2* __restrict__ dst) {
    extern __shared__ __align__(16) unsigned char smraw[];
    ull*    tw2 = (ull*)smraw;                       // [16][128] (c, -s)
    ull*    cc2 = tw2 + 2048;                        // (c,c)
    ull*    ss2 = cc2 + 128;                         // (s,s)
    float*  xs  = (float*)(smraw + 18432);           // [128][129]
    float2* T1  = (float2*)(smraw + 84480);          // [128][16]
    float*  ct  = (float*)(smraw + 100864);
    float*  st  = ct + 128;
    const int tid = threadIdx.x;                     // 256
    const float* x = src + (size_t)blockIdx.x * HW;

    if (tid < 128) {
        float a = (float)tid * (PI2/128.f);
        float c = cosf(a), s = sinf(a);
        ct[tid] = c; st[tid] = s;
        cc2[tid] = pk2(c, c); ss2[tid] = pk2(s, s);
    }
    for (int i = tid; i < HW; i += 256) xs[(i >> 7)*129 + (i & 127)] = x[i];
    __syncthreads();

    for (int i = tid; i < 2048; i += 256) {
        int idx = ((i >> 7) * (i & 127)) & 127;
        tw2[i] = pk2(ct[idx], -st[idx]);
    }
    __syncthreads();

    {   // phase 1 (radix-2 over w)
        int h = tid >> 1, m2b = (tid & 1) * 8;
        ull acc[8];
        #pragma unroll
        for (int j = 0; j < 8; j++) acc[j] = 0;
        const float* xr = xs + h*129;
        for (int w = 0; w < 64; w++) {
            float xa = xr[w], xb = xr[w + 64];
            float xp = xa + xb, xm = xa - xb;
            ull xp2 = pk2(xp, xp), xm2 = pk2(xm, xm);
            #pragma unroll
            for (int j = 0; j < 8; j++)
                FMA2(acc[j], (j & 1) ? xm2 : xp2, tw2[(m2b + j)*128 + w]);
        }
        #pragma unroll
        for (int j = 0; j < 8; j++) *(ull*)&T1[h*16 + m2b + j] = acc[j];
    }
    __syncthreads();

    // fold h: T1[h] <- T1[h]+T1[h+64], T1[h+64] <- T1[h]-T1[h+64]  (h<64)
    for (int it = tid; it < 1024; it += 256) {
        int h = it >> 4, m2 = it & 15;
        float2 A = T1[h*16 + m2], B = T1[(h + 64)*16 + m2];
        T1[h*16 + m2]        = make_float2(A.x + B.x, A.y + B.y);
        T1[(h + 64)*16 + m2] = make_float2(A.x - B.x, A.y - B.y);
    }
    __syncthreads();

    // phase 2: conjugate-pair fold over r; 64-iter loops
    {
        const int rp = tid >> 4, m2 = tid & 15;
        const float sc = 1.f/16384.f;
        const ull ONE2 = pk2(1.f, 1.f);
        const ull* Tb = (const ull*)T1 + m2;           // Tp rows (h<64)
        const size_t base = (size_t)blockIdx.x * NMODE;
        if (rp == 0) {
            ull ar = 0;
            #pragma unroll 4
            for (int h = 0; h < 64; h++) FMA2(ar, Tb[h*16], ONE2);
            float2 a = upk(ar);
            dst[base + m2] = make_float2(a.x*sc, a.y*sc);
            ull br = 0, bi = 0;
            #pragma unroll 4
            for (int h = 0; h < 64; h++) {
                int idx = (16*h) & 127;
                ull t = Tb[h*16];
                FMA2(br, t, cc2[idx]);
                FMA2(bi, t, ss2[idx]);
            }
            float2 r2 = upk(br), i2 = upk(bi);
            dst[base + 16*16 + m2] = make_float2((r2.x - i2.y)*sc, (r2.y + i2.x)*sc);
        } else {
            const ull* Ts = Tb + ((rp & 1) ? 64*16 : 0);   // odd r -> Tm
            ull ar = 0, ai = 0;
            #pragma unroll 4
            for (int h = 0; h < 64; h++) {
                int idx = (rp*h) & 127;
                ull t = Ts[h*16];
                FMA2(ar, t, cc2[idx]);
                FMA2(ai, t, ss2[idx]);
            }
            float2 a = upk(ar), b = upk(ai);
            dst[base + rp*16 + m2]        = make_float2((a.x + b.y)*sc, (a.y - b.x)*sc);
            dst[base + (32 - rp)*16 + m2] = make_float2((a.x - b.y)*sc, (a.y + b.x)*sc);
        }
    }
}

// ---------------- kqv spectral multiply ----------------
__global__ void k_spec_kqv(const float* __restrict__ w1r, const float* __restrict__ w1i,
                           const float* __restrict__ w2r, const float* __restrict__ w2i) {
    int s = blockIdx.x >> 9, n = blockIdx.x & 511;
    int m = threadIdx.x;                 // 512
    bool top = m < 256;
    int mm = top ? m : (m - 256);
    const float* wr = top ? w1r : w2r;
    const float* wi = top ? w1i : w2i;

    float2 xv[4];
    #pragma unroll
    for (int i = 0; i < 4; i++) xv[i] = g_XF[(size_t)(n*4 + i) * NMODE + m];

    #pragma unroll
    for (int o = 0; o < 4; o++) {
        float ax = 0.f, ay = 0.f;
        #pragma unroll
        for (int i = 0; i < 4; i++) {
            float a = wr[s*4096 + (i*4 + o)*256 + mm];
            float b = wi[s*4096 + (i*4 + o)*256 + mm];
            ax += xv[i].x*a - xv[i].y*b;
            ay += xv[i].x*b + xv[i].y*a;
        }
        g_OF[((size_t)(s*512 + n)*4 + o) * NMODE + m] = make_float2(ax, ay);
    }
}

// ---------------- kqv inverse partial DFT + pointwise skip -------------------
// byte layout: OFs 0..16384 | U ..81920 | S ..89600 | Dsw ..97280 | X0a ..97792
// | X16a ..98304 | X16s ..98816 | cc2 ..99840 | ss2 ..100864 | ct ..101376
// | st ..101888 | sk ..101952
static const int SM_IDFTK = 101952;

__global__ void __launch_bounds__(512, 2)
k_idft_kqv(const float* __restrict__ x, const float* __restrict__ skip) {
    extern __shared__ float sm[];
    float2* OFs  = (float2*)sm;                    // [4][32][16]
    float2* U    = OFs + 2048;                     // [4][128][16]
    ull*    S    = (ull*)(sm + 20480);             // [4][15][16]
    ull*    Dsw  = S + 960;
    ull*    X0a  = Dsw + 960;                      // [4][16]
    ull*    X16a = X0a + 64;
    ull*    X16s = X16a + 64;
    ull*    cc2  = X16s + 64;                      // [128] (c,c)
    ull*    ss2  = cc2 + 128;                      // [128] (s,s)
    float*  ct   = (float*)(ss2 + 128);
    float*  st   = ct + 128;
    float*  sk   = st + 128;                       // [4][4]
    const int tid = threadIdx.x;                   // 512
    const int s = blockIdx.x >> 9, n = blockIdx.x & 511;

    if (tid < 128) {
        float a = (float)tid * (PI2/128.f);
        float c = cosf(a), sn = sinf(a);
        ct[tid] = c; st[tid] = sn;
        cc2[tid] = pk2(c, c); ss2[tid] = pk2(sn, sn);
    }
    if (tid < 16)  sk[tid] = skip[s*16 + tid];
    for (int i = tid; i < 2048; i += 512)
        OFs[i] = g_OF[((size_t)(s*512 + n)*4) * NMODE + i];
    __syncthreads();

    // precompute conj-pair combos (scaled by a(m2))
    for (int it = tid; it < 960; it += 512) {
        int o = it / 240, rem = it % 240;
        int j = rem >> 4, m2 = rem & 15;  j += 1;       // j = 1..15
        float a = (m2 == 0) ? 1.f : 2.f;
        float2 Xp = OFs[o*512 + j*16 + m2];
        float2 Xn = OFs[o*512 + (32 - j)*16 + m2];
        S  [(o*15 + j - 1)*16 + m2] = pk2(a*(Xp.x + Xn.x), a*(Xp.y + Xn.y));
        float dx = a*(Xp.x - Xn.x), dy = a*(Xp.y - Xn.y);
        Dsw[(o*15 + j - 1)*16 + m2] = pk2(-dy, dx);     // i*D
    }
    if (tid < 192) {
        int o = (tid & 63) >> 4, m2 = tid & 15;
        float a = (m2 == 0) ? 1.f : 2.f;
        if (tid < 64) {
            float2 X = OFs[o*512 + m2];                         // m1i = 0
            X0a[o*16 + m2] = pk2(a*X.x, a*X.y);
        } else if (tid < 128) {
            float2 X = OFs[o*512 + 16*16 + m2];                 // m1i = 16
            X16a[o*16 + m2] = pk2(a*X.x, a*X.y);
        } else {
            float2 X = OFs[o*512 + 16*16 + m2];
            X16s[o*16 + m2] = pk2(a*X.y, -a*X.x);               // -i*X
        }
    }
    __syncthreads();

    // phase 1: conj-fold + h/h+64 fold. thread = (o, h<64, jh)
    {
        const int o  = tid >> 7;
        const int rem = tid & 127;
        const int h  = rem >> 1;
        const int jh = (rem & 1) * 8;
        ull Ue[8], Uo[8];
        const int i16 = (16*h) & 127;
        const ull c16 = cc2[i16], s16 = ss2[i16];
        const ull* X0p  = X0a  + o*16 + jh;
        const ull* X16p = X16a + o*16 + jh;
        const ull* X16q = X16s + o*16 + jh;
        #pragma unroll
        for (int j = 0; j < 8; j++) {
            Ue[j] = X0p[j];
            FMA2(Ue[j], X16p[j], c16);
            FMA2(Ue[j], X16q[j], s16);
            Uo[j] = 0;
        }
        #pragma unroll
        for (int jj = 1; jj <= 15; jj++) {
            int idx = (jj*h) & 127;
            ull cc = cc2[idx], ss = ss2[idx];
            const ull* Sp = S   + (o*15 + jj - 1)*16 + jh;
            const ull* Dp = Dsw + (o*15 + jj - 1)*16 + jh;
            if (jj & 1) {
                #pragma unroll
                for (int j = 0; j < 8; j++) { FMA2(Uo[j], Sp[j], cc); FMA2(Uo[j], Dp[j], ss); }
            } else {
                #pragma unroll
                for (int j = 0; j < 8; j++) { FMA2(Ue[j], Sp[j], cc); FMA2(Ue[j], Dp[j], ss); }
            }
        }
        #pragma unroll
        for (int j = 0; j < 8; j++) {
            float2 e = upk(Ue[j]), od = upk(Uo[j]);
            U[(o << 11) + (h << 4) + jh + j]        = make_float2(e.x + od.x, e.y + od.y);
            U[(o << 11) + ((h + 64) << 4) + jh + j] = make_float2(e.x - od.x, e.y - od.y);
        }
    }
    __syncthreads();

    // phase 2 (radix-2 over w) + skip
    const int wp = tid & 63, o = (tid >> 6) & 3, hh = tid >> 8;
    ull tw2[16];
    #pragma unroll
    for (int m2 = 0; m2 < 16; m2++) {
        int idx = (m2*wp) & 127;
        tw2[m2] = pk2(ct[idx], -st[idx]);
    }
    const float sk0 = sk[o*4+0], sk1 = sk[o*4+1], sk2 = sk[o*4+2], sk3 = sk[o*4+3];
    const size_t outbase = ((size_t)(s*512 + n)*4 + o) * HW;
    const size_t xbase   = (size_t)n * 4 * HW;

    for (int h = hh*64; h < hh*64 + 64; h++) {
        const ull* Ur = (const ull*)(U + (o << 11) + (h << 4));
        ull ae = 0, ao = 0;
        #pragma unroll
        for (int m2 = 0; m2 < 16; m2 += 2) {
            FMA2(ae, Ur[m2],     tw2[m2]);
            FMA2(ao, Ur[m2 + 1], tw2[m2 + 1]);
        }
        float2 re = upk(ae), ro = upk(ao);
        float ve = re.x + re.y, vo = ro.x + ro.y;
        float va = ve + vo, vb = ve - vo;
        int p = (h << 7) + wp;
        float x0 = x[xbase + p],           x1 = x[xbase + HW + p];
        float x2 = x[xbase + 2*HW + p],    x3 = x[xbase + 3*HW + p];
        float y0 = x[xbase + p + 64],      y1 = x[xbase + HW + p + 64];
        float y2 = x[xbase + 2*HW + p+64], y3 = x[xbase + 3*HW + p + 64];
        va += sk0*x0 + sk1*x1 + sk2*x2 + sk3*x3;
        vb += sk0*y0 + sk1*y1 + sk2*y2 + sk3*y3;
        g_kqv[outbase + p]      = va;
        g_kqv[outbase + p + 64] = vb;
    }
}

// ---------------- attention --------------------------------------------------
__global__ void k_zero() {
    g_S[blockIdx.x*256 + threadIdx.x] = 0.f;
}

static const int SM_SCORES = 2*64*130*4;   // 66560 B

__global__ void k_scores() {
    extern __shared__ float sm[];
    float* qs = sm;             // [64][130]
    float* ks = sm + 64*130;
    const int b = blockIdx.y, ch = blockIdx.x, tid = threadIdx.x;
    size_t qoff = ((size_t)512 + (size_t)b*64) * 65536 + (size_t)ch*128;
    size_t koff = ((size_t)b*64) * 65536 + (size_t)ch*128;
    for (int i = tid; i < 8192; i += 256) {
        int t = i >> 7, j = i & 127;
        qs[t*130 + j] = g_kqv[qoff + (size_t)t*65536 + j];
        ks[t*130 + j] = g_kqv[koff + (size_t)t*65536 + j];
    }
    __syncthreads();
    int t = tid >> 2, sl = tid & 3;
    ull acc[16];
    #pragma unroll
    for (int j = 0; j < 16; j++) acc[j] = 0;
    const ull* qrow = (const ull*)(qs + t*130);
    for (int kk = 0; kk < 64; kk++) {
        ull q2 = qrow[kk];
        #pragma unroll
        for (int j = 0; j < 16; j++) {
            ull k2 = *(const ull*)(ks + (sl + 4*j)*130 + 2*kk);
            FMA2(acc[j], q2, k2);
        }
    }
    #pragma unroll
    for (int j = 0; j < 16; j++) {
        float2 r = upk(acc[j]);
        atomicAdd(&g_S[(b*64 + t)*64 + sl + 4*j], (r.x + r.y) * (1.f/65536.f));
    }
}

__global__ void k_softmax() {
    int b = blockIdx.x, t = threadIdx.x;
    float* row = &g_S[(b*64 + t)*64];
    float mx = -1e30f;
    for (int s = 0; s < 64; s++) mx = fmaxf(mx, row[s]);
    float sum = 0.f;
    for (int s = 0; s < 64; s++) { float v = expf(row[s] - mx); row[s] = v; sum += v; }
    float inv = 1.f / sum;
    for (int s = 0; s < 64; s++) row[s] *= inv;
}

__global__ void k_attnv() {
    __shared__ ull As2[2048];
    const int b = blockIdx.y, z = blockIdx.z, tid = threadIdx.x;
    const int p = blockIdx.x * 512 + tid * 2;
    for (int i = tid; i < 2048; i += 256) {
        float a = g_S[b*4096 + z*2048 + i];
        As2[i] = pk2(a, a);
    }
    __syncthreads();
    ull acc[32];
    #pragma unroll
    for (int t = 0; t < 32; t++) acc[t] = 0;
    size_t vbase = ((size_t)1024 + (size_t)b*64) * 65536 + p;
    for (int s = 0; s < 64; s++) {
        ull vv = *(const ull*)(g_kqv + vbase + (size_t)s*65536);
        #pragma unroll
        for (int t = 0; t < 32; t++) FMA2(acc[t], vv, As2[t*64 + s]);
    }
    size_t obase = (size_t)b * 4194304 + (size_t)z * 32 * 65536 + p;
    #pragma unroll
    for (int t = 0; t < 32; t++) {
        float2 r = upk(acc[t]);
        *(float2*)(g_att + obase + (size_t)t*65536) = r;
    }
}

// ---------------- InstanceNorm2d + exact GELU --------------------------------
__global__ void k_inorm() {
    __shared__ float w1s[8], w2s[8];
    float* ptr = g_att + (size_t)blockIdx.x * HW;
    const int tid = threadIdx.x;
    float s1 = 0.f, s2 = 0.f;
    for (int i = tid; i < HW; i += 256) { float v = ptr[i]; s1 += v; s2 += v*v; }
    for (int off = 16; off; off >>= 1) {
        s1 += __shfl_down_sync(0xffffffffu, s1, off);
        s2 += __shfl_down_sync(0xffffffffu, s2, off);
    }
    if ((tid & 31) == 0) { w1s[tid >> 5] = s1; w2s[tid >> 5] = s2; }
    __syncthreads();
    if (tid == 0) {
        float a = 0.f, c = 0.f;
        for (int i = 0; i < 8; i++) { a += w1s[i]; c += w2s[i]; }
        w1s[0] = a * (1.f/HW); w2s[0] = c * (1.f/HW);
    }
    __syncthreads();
    float mu = w1s[0];
    float inv = rsqrtf(w2s[0] - mu*mu + 1e-5f);
    for (int i = tid; i < HW; i += 256) {
        float v = (ptr[i] - mu) * inv;
        ptr[i] = v * normcdff(v);
    }
}

// ---------------- end spectral multiply --------------------------------------
__global__ void k_spec_end(const float* __restrict__ w1r, const float* __restrict__ w1i,
                           const float* __restrict__ w2r, const float* __restrict__ w2i) {
    const int m = threadIdx.x;
    const int o0 = blockIdx.x * 2;
    bool top = m < 256;
    int mm = top ? m : (m - 256);
    const float* wr = top ? w1r : w2r;
    const float* wi = top ? w1i : w2i;
    ull r0[8], i0[8], r1[8], i1[8];
    #pragma unroll
    for (int b = 0; b < 8; b++) { r0[b]=0; i0[b]=0; r1[b]=0; i1[b]=0; }
    const ull* XF = (const ull*)g_XF + m;
    for (int i = 0; i < 256; i++) {
        float wr0 = wr[((size_t)i*256 + o0    )*256 + mm];
        float wi0 = wi[((size_t)i*256 + o0    )*256 + mm];
        float wr1 = wr[((size_t)i*256 + o0 + 1)*256 + mm];
        float wi1 = wi[((size_t)i*256 + o0 + 1)*256 + mm];
        ull wr02 = pk2(wr0, wr0), wi02 = pk2(wi0, wi0);
        ull wr12 = pk2(wr1, wr1), wi12 = pk2(wi1, wi1);
        #pragma unroll
        for (int b = 0; b < 8; b++) {
            ull X = XF[(size_t)(b*256 + i) * NMODE];
            FMA2(r0[b], X, wr02);  FMA2(i0[b], X, wi02);
            FMA2(r1[b], X, wr12);  FMA2(i1[b], X, wi12);
        }
    }
    #pragma unroll
    for (int b = 0; b < 8; b++) {
        float2 ar = upk(r0[b]), ai = upk(i0[b]);
        g_EOF[((size_t)(b*256 + o0    )) * NMODE + m] = make_float2(ar.x - ai.y, ai.x + ar.y);
        float2 br = upk(r1[b]), bi = upk(i1[b]);
        g_EOF[((size_t)(b*256 + o0 + 1)) * NMODE + m] = make_float2(br.x - bi.y, bi.x + br.y);
    }
}

// ---------------- end inverse partial DFT -> d_out ---------------------------
__global__ void k_idft_end(float* __restrict__ out) {
    __shared__ float2 OFs[512];
    __shared__ float2 U[2048];
    __shared__ ull Se[240], Dw[240], X0a[16], X16a[16], X16s[16];
    __shared__ ull cc2[128], ss2[128];
    __shared__ float ct[128], st[128];
    const int tid = threadIdx.x;               // 256
    const int plane = blockIdx.x;
    if (tid < 128) {
        float a = (float)tid * (PI2/128.f);
        float c = cosf(a), sn = sinf(a);
        ct[tid] = c; st[tid] = sn;
        cc2[tid] = pk2(c, c); ss2[tid] = pk2(sn, sn);
    }
    for (int i = tid; i < 512; i += 256) OFs[i] = g_EOF[(size_t)plane*512 + i];
    __syncthreads();

    if (tid < 240) {
        int j = (tid >> 4) + 1, m2 = tid & 15;
        float a = (m2 == 0) ? 1.f : 2.f;
        float2 Xp = OFs[j*16 + m2];
        float2 Xn = OFs[(32 - j)*16 + m2];
        Se[(j - 1)*16 + m2] = pk2(a*(Xp.x + Xn.x), a*(Xp.y + Xn.y));
        float dx = a*(Xp.x - Xn.x), dy = a*(Xp.y - Xn.y);
        Dw[(j - 1)*16 + m2] = pk2(-dy, dx);
    }
    if (tid < 16) {
        int m2 = tid;
        float a = (m2 == 0) ? 1.f : 2.f;
        float2 X0v = OFs[m2];
        float2 Xv  = OFs[16*16 + m2];
        X0a [m2] = pk2(a*X0v.x, a*X0v.y);
        X16a[m2] = pk2(a*Xv.x, a*Xv.y);
        X16s[m2] = pk2(a*Xv.y, -a*Xv.x);
    }
    __syncthreads();

    {   // phase 1: conj-fold + h/h+64 fold. thread = (h<64, jq of 4 m2)
        const int h  = tid >> 2;
        const int jq = (tid & 3) * 4;
        ull Ue[4], Uo[4];
        const int i16 = (16*h) & 127;
        const ull c16 = cc2[i16], s16 = ss2[i16];
        #pragma unroll
        for (int j = 0; j < 4; j++) {
            Ue[j] = X0a[jq + j];
            FMA2(Ue[j], X16a[jq + j], c16);
            FMA2(Ue[j], X16s[jq + j], s16);
            Uo[j] = 0;
        }
        #pragma unroll
        for (int jj = 1; jj <= 15; jj++) {
            int idx = (jj*h) & 127;
            ull cc = cc2[idx], ss = ss2[idx];
            const ull* Sp = Se + (jj - 1)*16 + jq;
            const ull* Dp = Dw + (jj - 1)*16 + jq;
            if (jj & 1) {
                #pragma unroll
                for (int j = 0; j < 4; j++) { FMA2(Uo[j], Sp[j], cc); FMA2(Uo[j], Dp[j], ss); }
            } else {
                #pragma unroll
                for (int j = 0; j < 4; j++) { FMA2(Ue[j], Sp[j], cc); FMA2(Ue[j], Dp[j], ss); }
            }
        }
        #pragma unroll
        for (int j = 0; j < 4; j++) {
            float2 e = upk(Ue[j]), od = upk(Uo[j]);
            U[(h << 4) + jq + j]        = make_float2(e.x + od.x, e.y + od.y);
            U[((h + 64) << 4) + jq + j] = make_float2(e.x - od.x, e.y - od.y);
        }
    }
    __syncthreads();

    // phase 2 (radix-2 over w)
    const int wp = tid & 63, hq = tid >> 6;
    ull tw2[16];
    #pragma unroll
    for (int m2 = 0; m2 < 16; m2++) {
        int idx = (m2*wp) & 127;
        tw2[m2] = pk2(ct[idx], -st[idx]);
    }
    for (int h = hq*32; h < hq*32 + 32; h++) {
        const ull* Ur = (const ull*)(U + (h << 4));
        ull ae = 0, ao = 0;
        #pragma unroll
        for (int m2 = 0; m2 < 16; m2 += 2) {
            FMA2(ae, Ur[m2],     tw2[m2]);
            FMA2(ao, Ur[m2 + 1], tw2[m2 + 1]);
        }
        float2 re = upk(ae), ro = upk(ao);
        float ve = re.x + re.y, vo = ro.x + ro.y;
        size_t base = (size_t)plane*HW + (h << 7) + wp;
        out[base]      = ve + vo;
        out[base + 64] = ve - vo;
    }
}

// ---------------- end pointwise skip GEMM ------------------------------------
static const int SM_ENDSK = 32*128*8 + 32*128*4;   // 49152 B

__global__ void k_endskip(const float* __restrict__ skip, float* __restrict__ out) {
    extern __shared__ __align__(16) unsigned char smraw[];
    ull*   Ssp = (ull*)smraw;
    float* Gs  = (float*)(Ssp + 4096);
    const int b = blockIdx.z, o0 = blockIdx.y * 128, p0 = blockIdx.x * 128;
    const int tid = threadIdx.x;
    const int oy = tid >> 4, px = tid & 15;
    ull acc[8][4];
    #pragma unroll
    for (int j = 0; j < 8; j++)
        #pragma unroll
        for (int jj = 0; jj < 4; jj++) acc[j][jj] = 0;

    for (int kc = 0; kc < 256; kc += 32) {
        for (int i = tid; i < 4096; i += 256) {
            int o = i & 127, k = i >> 7;
            float s = skip[(size_t)(o0 + o)*256 + kc + k];
            Ssp[k*128 + o] = pk2(s, s);
        }
        for (int i = tid; i < 4096; i += 256) {
            int c = i & 127, ir = i >> 7;
            Gs[ir*128 + c] = g_att[((size_t)b*256 + kc + ir) * HW + p0 + c];
        }
        __syncthreads();
        #pragma unroll 4
        for (int k = 0; k < 32; k++) {
            ull gv[4];
            const ull* gp = (const ull*)(Gs + k*128);
            #pragma unroll
            for (int jj = 0; jj < 4; jj++) gv[jj] = gp[px + 16*jj];
            #pragma unroll
            for (int j = 0; j < 8; j++) {
                ull sv = Ssp[k*128 + oy + 16*j];
                #pragma unroll
                for (int jj = 0; jj < 4; jj++) FMA2(acc[j][jj], gv[jj], sv);
            }
        }
        __syncthreads();
    }
    #pragma unroll
    for (int j = 0; j < 8; j++)
        #pragma unroll
        for (int jj = 0; jj < 4; jj++) {
            size_t oidx = ((size_t)b*256 + o0 + oy + 16*j) * HW + p0 + 2*px + 32*jj;
            float2 r = upk(acc[j][jj]);
            float2* op = (float2*)(out + oidx);
            float2 cur = *op;
            cur.x += r.x; cur.y += r.y;
            *op = cur;
        }
}

// ---------------- launch -----------------------------------------------------
extern "C" void kernel_launch(void* const* d_in, const int* in_sizes, int n_in,
                              void* d_out, int out_size) {
    const float* x        = (const float*)d_in[0];
    const float* kqv_w1r  = (const float*)d_in[1];
    const float* kqv_w1i  = (const float*)d_in[2];
    const float* kqv_w2r  = (const float*)d_in[3];
    const float* kqv_w2i  = (const float*)d_in[4];
    const float* kqv_skip = (const float*)d_in[5];
    const float* end_w1r  = (const float*)d_in[6];
    const float* end_w1i  = (const float*)d_in[7];
    const float* end_w2r  = (const float*)d_in[8];
    const float* end_w2i  = (const float*)d_in[9];
    const float* end_skip = (const float*)d_in[10];
    float* out = (float*)d_out;

    cudaFuncSetAttribute(k_fwd_dft,  cudaFuncAttributeMaxDynamicSharedMemorySize, SM_FWD);
    cudaFuncSetAttribute(k_idft_kqv, cudaFuncAttributeMaxDynamicSharedMemorySize, SM_IDFTK);
    cudaFuncSetAttribute(k_scores,   cudaFuncAttributeMaxDynamicSharedMemorySize, SM_SCORES);
    cudaFuncSetAttribute(k_endskip,  cudaFuncAttributeMaxDynamicSharedMemorySize, SM_ENDSK);

    float2* gXF;  cudaGetSymbolAddress((void**)&gXF,  g_XF);
    float*  gAtt; cudaGetSymbolAddress((void**)&gAtt, g_att);

    // slot #4 profiled -> k_idft_kqv
    k_zero<<<128, 256>>>();                                         // 1
    k_fwd_dft<<<2048, 256, SM_FWD>>>(x, gXF);                       // 2
    k_spec_kqv<<<1536, 512>>>(kqv_w1r, kqv_w1i, kqv_w2r, kqv_w2i);  // 3
    k_idft_kqv<<<1536, 512, SM_IDFTK>>>(x, kqv_skip);               // 4 <- profiled

    k_scores<<<dim3(512, 8), 256, SM_SCORES>>>();
    k_softmax<<<8, 64>>>();
    k_attnv<<<dim3(128, 8, 2), 256>>>();

    k_inorm<<<2048, 256>>>();

    k_fwd_dft<<<2048, 256, SM_FWD>>>(gAtt, gXF);
    k_spec_end<<<128, 512>>>(end_w1r, end_w1i, end_w2r, end_w2i);
    k_idft_end<<<2048, 256>>>(out);
    k_endskip<<<dim3(128, 2, 8), 256, SM_ENDSK>>>(end_skip, out);
}